// round 4
// baseline (speedup 1.0000x reference)
#include <cuda_runtime.h>
#include <cuda_fp16.h>
#include <mma.h>
#include <cstdint>

using namespace nvcuda;

#define NN   50000
#define EE   800000
#define HH   128
#define GG   64
#define OUTD 10

// ---------------- scratch (device globals; no dynamic allocation) ----------
__device__ __half g_h16a[(size_t)NN * HH];   // gemm input / gather output
__device__ __half g_h16b[(size_t)NN * HH];   // gemm output / gather input
__device__ __half g_w16[3 * HH * HH];        // fp16 weights
__device__ int    g_src[EE];
__device__ int    g_dst[EE];
__device__ int    g_batch[NN];
__device__ int    g_deg[NN];
__device__ int    g_rowstart[NN + 1];
__device__ int    g_cursor[NN];
__device__ float  g_dinv[NN];
__device__ int2   g_csr[EE];                 // packed (src, w-as-int)
__device__ float  g_pooled[GG * HH];
__device__ float  g_cnts[GG];
__device__ int    g_is64;

// ---------------- setup -----------------------------------------------------
__global__ void k_zero() {
    int i = blockIdx.x * blockDim.x + threadIdx.x;
    if (i < NN) g_deg[i] = 0;
    if (i < GG * HH) g_pooled[i] = 0.0f;
    if (i < GG) g_cnts[i] = 0.0f;
}

__global__ void k_detect(const int* __restrict__ p) {
    __shared__ int any;
    if (threadIdx.x == 0) any = 0;
    __syncthreads();
    int v = 0;
    for (int i = threadIdx.x; i < 4096; i += blockDim.x) v |= p[2 * i + 1];
    if (v) atomicOr(&any, 1);
    __syncthreads();
    if (threadIdx.x == 0) g_is64 = any ? 0 : 1;
}

// convert edges to int32 AND build degree histogram in one pass
__global__ void k_cvt_edges(const void* __restrict__ p) {
    int e = blockIdx.x * blockDim.x + threadIdx.x;
    if (e >= EE) return;
    int s, d;
    if (g_is64) {
        const long long* q = (const long long*)p;
        s = (int)q[e];
        d = (int)q[EE + e];
    } else {
        const int* q = (const int*)p;
        s = q[e];
        d = q[EE + e];
    }
    s = min(max(s, 0), NN - 1);
    d = min(max(d, 0), NN - 1);
    g_src[e] = s;
    g_dst[e] = d;
    atomicAdd(&g_deg[d], 1);
}

// convert batch AND count nodes-per-graph in one pass
__global__ void k_cvt_batch(const void* __restrict__ p) {
    int n = blockIdx.x * blockDim.x + threadIdx.x;
    if (n >= NN) return;
    int b;
    if (g_is64) b = (int)((const long long*)p)[n];
    else        b = ((const int*)p)[n];
    b = min(max(b, 0), GG - 1);
    g_batch[n] = b;
    atomicAdd(&g_cnts[b], 1.0f);
}

// convert x (N*128) and all three weight matrices to fp16, vectorized x4
__global__ void k_cvtx(const float* __restrict__ x,
                       const float* __restrict__ W0,
                       const float* __restrict__ W1,
                       const float* __restrict__ W2) {
    const int XQ = NN * HH / 4;          // 1,600,000 float4s
    const int WQ = HH * HH / 4;          // 4096 float4s per weight
    int i = blockIdx.x * blockDim.x + threadIdx.x;
    const float4* src;
    uint2* dst;
    int off;
    if (i < XQ) {
        src = (const float4*)x; dst = (uint2*)g_h16a; off = i;
    } else if (i < XQ + WQ) {
        src = (const float4*)W0; dst = (uint2*)g_w16; off = i - XQ;
    } else if (i < XQ + 2 * WQ) {
        src = (const float4*)W1; dst = (uint2*)(g_w16 + HH * HH); off = i - XQ - WQ;
    } else if (i < XQ + 3 * WQ) {
        src = (const float4*)W2; dst = (uint2*)(g_w16 + 2 * HH * HH); off = i - XQ - 2 * WQ;
    } else return;
    float4 v = src[off];
    __half2 a = __floats2half2_rn(v.x, v.y);
    __half2 b = __floats2half2_rn(v.z, v.w);
    uint2 o;
    o.x = *(unsigned int*)&a;
    o.y = *(unsigned int*)&b;
    dst[off] = o;
}

// single-block scan of g_deg -> g_rowstart; also emits cursor + dinv
__global__ void k_scan() {
    __shared__ int part[1024];
    const int CHUNK = 49;
    int t = threadIdx.x;
    int base = t * CHUNK;
    int s = 0;
    for (int i = 0; i < CHUNK; i++) {
        int idx = base + i;
        if (idx < NN) s += g_deg[idx];
    }
    part[t] = s;
    __syncthreads();
    for (int off = 1; off < 1024; off <<= 1) {
        int v = (t >= off) ? part[t - off] : 0;
        __syncthreads();
        part[t] += v;
        __syncthreads();
    }
    int run = (t == 0) ? 0 : part[t - 1];
    for (int i = 0; i < CHUNK; i++) {
        int idx = base + i;
        if (idx <= NN) {
            g_rowstart[idx] = run;
            if (idx < NN) {
                int dg = g_deg[idx];
                g_cursor[idx] = run;
                g_dinv[idx] = rsqrtf((float)dg + 1.0f);
                run += dg;
            }
        }
    }
}

__global__ void k_fill() {
    int e = blockIdx.x * blockDim.x + threadIdx.x;
    if (e < EE) {
        int s = g_src[e];
        int d = g_dst[e];
        float w = g_dinv[s] * g_dinv[d];
        int pos = atomicAdd(&g_cursor[d], 1);
        g_csr[pos] = make_int2(s, __float_as_int(w));
    }
}

// ---------------- tensor-core GEMM: C[N,128](f16) = A[N,128](f16) @ W(f16) --
// block = 256 threads (8 warps), tile 128x128; warp tile 32x64 (2x4 wmma).
__global__ void __launch_bounds__(256) k_gemm(const __half* __restrict__ A,
                                              const __half* __restrict__ W,
                                              __half* __restrict__ C,
                                              int nRows) {
    __shared__ __align__(32) __half As[128][144];        // 36,864 B
    __shared__ __align__(32) float  stage[8][256];       //  8,192 B

    int tid  = threadIdx.x;
    int w    = tid >> 5;
    int lane = tid & 31;
    int row0 = blockIdx.x * 128;

    // load A tile (128 x 128 halves) as uint4 (8 halves each)
#pragma unroll
    for (int i = 0; i < 8; i++) {
        int idx = tid + i * 256;          // 0..2047
        int r  = idx >> 4;                // 0..127
        int c8 = idx & 15;                // 16 uint4 per row
        uint4 v = make_uint4(0u, 0u, 0u, 0u);
        if (row0 + r < nRows)
            v = *(const uint4*)(A + (size_t)(row0 + r) * 128 + c8 * 8);
        *(uint4*)&As[r][c8 * 8] = v;
    }
    __syncthreads();

    int wr = w >> 1;                      // 0..3 : row block of 32
    int wc = w & 1;                       // 0..1 : col block of 64
    int r0w = wr * 32;
    int c0w = wc * 64;

    wmma::fragment<wmma::accumulator, 16, 16, 16, float> c[2][4];
#pragma unroll
    for (int i = 0; i < 2; i++)
#pragma unroll
        for (int j = 0; j < 4; j++) wmma::fill_fragment(c[i][j], 0.0f);

#pragma unroll
    for (int k0 = 0; k0 < 128; k0 += 16) {
        wmma::fragment<wmma::matrix_a, 16, 16, 16, __half, wmma::row_major> a[2];
        wmma::fragment<wmma::matrix_b, 16, 16, 16, __half, wmma::row_major> b[4];
#pragma unroll
        for (int i = 0; i < 2; i++)
            wmma::load_matrix_sync(a[i], &As[r0w + i * 16][k0], 144);
#pragma unroll
        for (int j = 0; j < 4; j++)
            wmma::load_matrix_sync(b[j], W + (size_t)k0 * 128 + c0w + j * 16, 128);
#pragma unroll
        for (int i = 0; i < 2; i++)
#pragma unroll
            for (int j = 0; j < 4; j++)
                wmma::mma_sync(c[i][j], a[i], b[j], c[i][j]);
    }

    // store: per-warp stage 16x16 floats -> fp16 global
#pragma unroll
    for (int i = 0; i < 2; i++) {
#pragma unroll
        for (int j = 0; j < 4; j++) {
            wmma::store_matrix_sync(&stage[w][0], c[i][j], 16, wmma::mem_row_major);
            __syncwarp();
            const float* sp = &stage[w][lane * 8];
            float f0 = sp[0], f1 = sp[1], f2 = sp[2], f3 = sp[3];
            float f4 = sp[4], f5 = sp[5], f6 = sp[6], f7 = sp[7];
            __half2 p0 = __floats2half2_rn(f0, f1);
            __half2 p1 = __floats2half2_rn(f2, f3);
            __half2 p2 = __floats2half2_rn(f4, f5);
            __half2 p3 = __floats2half2_rn(f6, f7);
            uint4 pv;
            pv.x = *(unsigned int*)&p0;
            pv.y = *(unsigned int*)&p1;
            pv.z = *(unsigned int*)&p2;
            pv.w = *(unsigned int*)&p3;
            int gr = row0 + r0w + i * 16 + (lane >> 1);
            if (gr < nRows)
                *(uint4*)&C[(size_t)gr * 128 + c0w + j * 16 + (lane & 1) * 8] = pv;
            __syncwarp();
        }
    }
}

// ---------------- CSR gather (fp16 in, fp16 out, fused relu) ----------------
__device__ __forceinline__ float4 h4conv(uint2 v) {
    __half2 a = *(__half2*)&v.x;
    __half2 b = *(__half2*)&v.y;
    float2 fa = __half22float2(a);
    float2 fb = __half22float2(b);
    return make_float4(fa.x, fa.y, fb.x, fb.y);
}

__global__ void __launch_bounds__(256) k_gather(const __half* __restrict__ h,
                                                __half* __restrict__ out,
                                                int doRelu) {
    int warp = (blockIdx.x * blockDim.x + threadIdx.x) >> 5;
    int lane = threadIdx.x & 31;
    if (warp >= NN) return;
    int n = warp;

    const uint2* h2 = (const uint2*)h;
    float di = g_dinv[n];
    float sw = di * di;
    float4 hv = h4conv(h2[(size_t)n * 32 + lane]);
    float4 acc = make_float4(hv.x * sw, hv.y * sw, hv.z * sw, hv.w * sw);

    int i   = g_rowstart[n];
    int end = g_rowstart[n + 1];
    for (; i + 3 < end; i += 4) {
        int2 e0 = g_csr[i], e1 = g_csr[i + 1], e2 = g_csr[i + 2], e3 = g_csr[i + 3];
        float4 v0 = h4conv(h2[(size_t)e0.x * 32 + lane]);
        float4 v1 = h4conv(h2[(size_t)e1.x * 32 + lane]);
        float4 v2 = h4conv(h2[(size_t)e2.x * 32 + lane]);
        float4 v3 = h4conv(h2[(size_t)e3.x * 32 + lane]);
        float w0 = __int_as_float(e0.y), w1 = __int_as_float(e1.y);
        float w2 = __int_as_float(e2.y), w3 = __int_as_float(e3.y);
        acc.x += w0 * v0.x + w1 * v1.x + w2 * v2.x + w3 * v3.x;
        acc.y += w0 * v0.y + w1 * v1.y + w2 * v2.y + w3 * v3.y;
        acc.z += w0 * v0.z + w1 * v1.z + w2 * v2.z + w3 * v3.z;
        acc.w += w0 * v0.w + w1 * v1.w + w2 * v2.w + w3 * v3.w;
    }
    for (; i < end; i++) {
        int2 e0 = g_csr[i];
        float w0 = __int_as_float(e0.y);
        float4 v0 = h4conv(h2[(size_t)e0.x * 32 + lane]);
        acc.x += w0 * v0.x; acc.y += w0 * v0.y;
        acc.z += w0 * v0.z; acc.w += w0 * v0.w;
    }
    if (doRelu) {
        acc.x = fmaxf(acc.x, 0.f); acc.y = fmaxf(acc.y, 0.f);
        acc.z = fmaxf(acc.z, 0.f); acc.w = fmaxf(acc.w, 0.f);
    }
    __half2 p0 = __floats2half2_rn(acc.x, acc.y);
    __half2 p1 = __floats2half2_rn(acc.z, acc.w);
    uint2 o;
    o.x = *(unsigned int*)&p0;
    o.y = *(unsigned int*)&p1;
    ((uint2*)out)[(size_t)n * 32 + lane] = o;
}

// ---------------- pooling (fp16 in) -----------------------------------------
__global__ void __launch_bounds__(128) k_pool(const __half* __restrict__ h) {
    int d = threadIdx.x;
    int n0 = blockIdx.x * 256;
    int n1 = n0 + 256; if (n1 > NN) n1 = NN;
    if (n0 >= NN) return;
    float acc = 0.0f;
    int g = g_batch[n0];
    for (int n = n0; n < n1; n++) {
        int b = g_batch[n];
        if (b != g) {
            atomicAdd(&g_pooled[g * HH + d], acc);
            acc = 0.0f;
            g = b;
        }
        acc += __half2float(h[(size_t)n * HH + d]);
    }
    atomicAdd(&g_pooled[g * HH + d], acc);
}

// ---------------- final MLP (single block) ----------------------------------
__global__ void __launch_bounds__(256) k_mlp(const float* __restrict__ M0w,
                                             const float* __restrict__ M0b,
                                             const float* __restrict__ M1w,
                                             const float* __restrict__ M1b,
                                             float* __restrict__ out) {
    __shared__ float pv[GG * HH];
    int t = threadIdx.x;
    for (int i = t; i < GG * HH; i += 256) {
        int g = i >> 7;
        pv[i] = g_pooled[i] / fmaxf(g_cnts[g], 1.0f);
    }
    __syncthreads();
    float hid[32];
#pragma unroll
    for (int i = 0; i < 32; i++) {
        int idx = t + 256 * i;
        int g = idx >> 7, j = idx & 127;
        float s = M0b[j];
        for (int k = 0; k < 128; k++) s += pv[(g << 7) + k] * M0w[k * 128 + j];
        hid[i] = fmaxf(s, 0.0f);
    }
    __syncthreads();
#pragma unroll
    for (int i = 0; i < 32; i++) pv[t + 256 * i] = hid[i];
    __syncthreads();
    for (int o = t; o < GG * OUTD; o += 256) {
        int g = o / OUTD, c = o % OUTD;
        float s = M1b[c];
        for (int j = 0; j < 128; j++) s += pv[(g << 7) + j] * M1w[j * OUTD + c];
        out[o] = s;
    }
}

// ---------------- launch ----------------------------------------------------
extern "C" void kernel_launch(void* const* d_in, const int* in_sizes, int n_in,
                              void* d_out, int out_size) {
    const float* x   = (const float*)d_in[0];
    const float* W0  = (const float*)d_in[1];
    const float* W1  = (const float*)d_in[2];
    const float* W2  = (const float*)d_in[3];
    const float* M0w = (const float*)d_in[4];
    const float* M0b = (const float*)d_in[5];
    const float* M1w = (const float*)d_in[6];
    const float* M1b = (const float*)d_in[7];
    const void*  ei  = d_in[8];
    const void*  bat = d_in[9];
    float* out = (float*)d_out;

    __half* hA = nullptr;
    __half* hB = nullptr;
    __half* w16 = nullptr;
    cudaGetSymbolAddress((void**)&hA, g_h16a);
    cudaGetSymbolAddress((void**)&hB, g_h16b);
    cudaGetSymbolAddress((void**)&w16, g_w16);

    const int T = 256;
    int gN = (NN + T - 1) / T;              // 196
    int gE = (EE + T - 1) / T;              // 3125
    int gGemm   = (NN + 127) / 128;         // 391
    int gGather = (NN * 32 + T - 1) / T;    // 6250
    int gCvt    = (NN * HH / 4 + 3 * HH * HH / 4 + T - 1) / T;

    k_zero<<<gN, T>>>();
    k_detect<<<1, 256>>>((const int*)ei);
    k_cvt_edges<<<gE, T>>>(ei);
    k_cvt_batch<<<gN, T>>>(bat);
    k_cvtx<<<gCvt, T>>>(x, W0, W1, W2);
    k_scan<<<1, 1024>>>();
    k_fill<<<gE, T>>>();

    // layer 1: A=x16 (hA) -> gemm -> hB -> gather(relu) -> hA
    k_gemm<<<gGemm, T>>>(hA, w16, hB, NN);
    k_gather<<<gGather, T>>>(hB, hA, 1);
    // layer 2
    k_gemm<<<gGemm, T>>>(hA, w16 + HH * HH, hB, NN);
    k_gather<<<gGather, T>>>(hB, hA, 1);
    // layer 3 (no relu on final h)
    k_gemm<<<gGemm, T>>>(hA, w16 + 2 * HH * HH, hB, NN);
    k_gather<<<gGather, T>>>(hB, hA, 0);

    k_pool<<<(NN + 255) / 256, 128>>>(hA);
    k_mlp<<<1, 256>>>(M0w, M0b, M1w, M1b, out);
}

// round 5
// speedup vs baseline: 1.0506x; 1.0506x over previous
#include <cuda_runtime.h>
#include <cuda_fp16.h>
#include <mma.h>
#include <cstdint>

using namespace nvcuda;

#define NN   50000
#define EE   800000
#define HH   128
#define GG   64
#define OUTD 10

// ---------------- scratch (device globals; no dynamic allocation) ----------
__device__ __half g_h16a[(size_t)NN * HH];   // gemm input / gather output
__device__ __half g_h16b[(size_t)NN * HH];   // gemm output / gather input
__device__ __half g_w16[3 * HH * HH];        // fp16 weights
__device__ int    g_src[EE];
__device__ int    g_dst[EE];
__device__ int    g_batch[NN];
__device__ int    g_deg[NN];
__device__ int    g_rowstart[NN + 1];
__device__ int    g_cursor[NN];
__device__ float  g_dinv[NN];
__device__ int2   g_csr[EE];                 // packed (src, w-as-int)
__device__ float  g_pooled[GG * HH];
__device__ float  g_cnts[GG];
__device__ int    g_is64;

// ---------------- setup -----------------------------------------------------
__global__ void k_zero() {
    int i = blockIdx.x * blockDim.x + threadIdx.x;
    if (i < NN) g_deg[i] = 0;
    if (i < GG * HH) g_pooled[i] = 0.0f;
    if (i < GG) g_cnts[i] = 0.0f;
}

// weights-only fp32 -> fp16 (3 * 128*128 = 49152 floats = 12288 float4)
__global__ void k_cvtw(const float* __restrict__ W0,
                       const float* __restrict__ W1,
                       const float* __restrict__ W2) {
    const int WQ = HH * HH / 4;          // 4096
    int i = blockIdx.x * blockDim.x + threadIdx.x;
    if (i >= 3 * WQ) return;
    const float4* src;
    int off;
    if (i < WQ)          { src = (const float4*)W0; off = i; }
    else if (i < 2 * WQ) { src = (const float4*)W1; off = i - WQ; }
    else                 { src = (const float4*)W2; off = i - 2 * WQ; }
    float4 v = src[off];
    __half2 a = __floats2half2_rn(v.x, v.y);
    __half2 b = __floats2half2_rn(v.z, v.w);
    uint2 o;
    o.x = *(unsigned int*)&a;
    o.y = *(unsigned int*)&b;
    ((uint2*)g_w16)[i] = o;
}

__global__ void k_detect(const int* __restrict__ p) {
    __shared__ int any;
    if (threadIdx.x == 0) any = 0;
    __syncthreads();
    int v = 0;
    for (int i = threadIdx.x; i < 4096; i += blockDim.x) v |= p[2 * i + 1];
    if (v) atomicOr(&any, 1);
    __syncthreads();
    if (threadIdx.x == 0) g_is64 = any ? 0 : 1;
}

// convert edges to int32 AND build degree histogram in one pass
__global__ void k_cvt_edges(const void* __restrict__ p) {
    int e = blockIdx.x * blockDim.x + threadIdx.x;
    if (e >= EE) return;
    int s, d;
    if (g_is64) {
        const long long* q = (const long long*)p;
        s = (int)q[e];
        d = (int)q[EE + e];
    } else {
        const int* q = (const int*)p;
        s = q[e];
        d = q[EE + e];
    }
    s = min(max(s, 0), NN - 1);
    d = min(max(d, 0), NN - 1);
    g_src[e] = s;
    g_dst[e] = d;
    atomicAdd(&g_deg[d], 1);
}

// convert batch AND count nodes-per-graph, warp-aggregated (batch is sorted:
// nearly all lanes share one graph -> 1 atomic per warp instead of 32).
__global__ void k_cvt_batch(const void* __restrict__ p) {
    int n = blockIdx.x * blockDim.x + threadIdx.x;
    if (n >= NN) return;
    int b;
    if (g_is64) b = (int)((const long long*)p)[n];
    else        b = ((const int*)p)[n];
    b = min(max(b, 0), GG - 1);
    g_batch[n] = b;
    unsigned am = __activemask();
    unsigned mask = __match_any_sync(am, b);
    int leader = __ffs(mask) - 1;
    if ((threadIdx.x & 31) == leader)
        atomicAdd(&g_cnts[b], (float)__popc(mask));
}

// single-block scan of g_deg -> g_rowstart; also emits cursor + dinv
__global__ void k_scan() {
    __shared__ int part[1024];
    const int CHUNK = 49;
    int t = threadIdx.x;
    int base = t * CHUNK;
    int s = 0;
    for (int i = 0; i < CHUNK; i++) {
        int idx = base + i;
        if (idx < NN) s += g_deg[idx];
    }
    part[t] = s;
    __syncthreads();
    for (int off = 1; off < 1024; off <<= 1) {
        int v = (t >= off) ? part[t - off] : 0;
        __syncthreads();
        part[t] += v;
        __syncthreads();
    }
    int run = (t == 0) ? 0 : part[t - 1];
    for (int i = 0; i < CHUNK; i++) {
        int idx = base + i;
        if (idx <= NN) {
            g_rowstart[idx] = run;
            if (idx < NN) {
                int dg = g_deg[idx];
                g_cursor[idx] = run;
                g_dinv[idx] = rsqrtf((float)dg + 1.0f);
                run += dg;
            }
        }
    }
}

__global__ void k_fill() {
    int e = blockIdx.x * blockDim.x + threadIdx.x;
    if (e < EE) {
        int s = g_src[e];
        int d = g_dst[e];
        float w = g_dinv[s] * g_dinv[d];
        int pos = atomicAdd(&g_cursor[d], 1);
        g_csr[pos] = make_int2(s, __float_as_int(w));
    }
}

// ---------------- tensor-core GEMM core (shared by fp16/fp32-A variants) ----
template <typename LOADA>
__device__ __forceinline__ void gemm_body(LOADA loadA,
                                          const __half* __restrict__ W,
                                          __half* __restrict__ C,
                                          int nRows) {
    __shared__ __align__(32) __half As[128][144];        // 36,864 B
    __shared__ __align__(32) float  stage[8][256];       //  8,192 B

    int tid  = threadIdx.x;
    int w    = tid >> 5;
    int lane = tid & 31;
    int row0 = blockIdx.x * 128;

    loadA(As, row0, tid, nRows);
    __syncthreads();

    int wr = w >> 1;
    int wc = w & 1;
    int r0w = wr * 32;
    int c0w = wc * 64;

    wmma::fragment<wmma::accumulator, 16, 16, 16, float> c[2][4];
#pragma unroll
    for (int i = 0; i < 2; i++)
#pragma unroll
        for (int j = 0; j < 4; j++) wmma::fill_fragment(c[i][j], 0.0f);

#pragma unroll
    for (int k0 = 0; k0 < 128; k0 += 16) {
        wmma::fragment<wmma::matrix_a, 16, 16, 16, __half, wmma::row_major> a[2];
        wmma::fragment<wmma::matrix_b, 16, 16, 16, __half, wmma::row_major> b[4];
#pragma unroll
        for (int i = 0; i < 2; i++)
            wmma::load_matrix_sync(a[i], &As[r0w + i * 16][k0], 144);
#pragma unroll
        for (int j = 0; j < 4; j++)
            wmma::load_matrix_sync(b[j], W + (size_t)k0 * 128 + c0w + j * 16, 128);
#pragma unroll
        for (int i = 0; i < 2; i++)
#pragma unroll
            for (int j = 0; j < 4; j++)
                wmma::mma_sync(c[i][j], a[i], b[j], c[i][j]);
    }

#pragma unroll
    for (int i = 0; i < 2; i++) {
#pragma unroll
        for (int j = 0; j < 4; j++) {
            wmma::store_matrix_sync(&stage[w][0], c[i][j], 16, wmma::mem_row_major);
            __syncwarp();
            const float* sp = &stage[w][lane * 8];
            __half2 p0 = __floats2half2_rn(sp[0], sp[1]);
            __half2 p1 = __floats2half2_rn(sp[2], sp[3]);
            __half2 p2 = __floats2half2_rn(sp[4], sp[5]);
            __half2 p3 = __floats2half2_rn(sp[6], sp[7]);
            uint4 pv;
            pv.x = *(unsigned int*)&p0;
            pv.y = *(unsigned int*)&p1;
            pv.z = *(unsigned int*)&p2;
            pv.w = *(unsigned int*)&p3;
            int gr = row0 + r0w + i * 16 + (lane >> 1);
            if (gr < nRows)
                *(uint4*)&C[(size_t)gr * 128 + c0w + j * 16 + (lane & 1) * 8] = pv;
            __syncwarp();
        }
    }
}

// fp16-A GEMM (layers 2, 3)
__global__ void __launch_bounds__(256) k_gemm(const __half* __restrict__ A,
                                              const __half* __restrict__ W,
                                              __half* __restrict__ C,
                                              int nRows) {
    gemm_body([A](__half (*As)[144], int row0, int tid, int nR) {
#pragma unroll
        for (int i = 0; i < 8; i++) {
            int idx = tid + i * 256;
            int r  = idx >> 4;
            int c8 = idx & 15;
            uint4 v = make_uint4(0u, 0u, 0u, 0u);
            if (row0 + r < nR)
                v = *(const uint4*)(A + (size_t)(row0 + r) * 128 + c8 * 8);
            *(uint4*)&As[r][c8 * 8] = v;
        }
    }, W, C, nRows);
}

// fp32-A GEMM (layer 1: reads x directly, converts in smem-load phase)
__global__ void __launch_bounds__(256) k_gemm_f32in(const float* __restrict__ A,
                                                    const __half* __restrict__ W,
                                                    __half* __restrict__ C,
                                                    int nRows) {
    gemm_body([A](__half (*As)[144], int row0, int tid, int nR) {
#pragma unroll
        for (int i = 0; i < 16; i++) {
            int idx = tid + i * 256;      // 0..4095 float4s
            int r  = idx >> 5;            // row (32 float4 per row)
            int c4 = idx & 31;
            float4 v = make_float4(0.f, 0.f, 0.f, 0.f);
            if (row0 + r < nR)
                v = *(const float4*)(A + (size_t)(row0 + r) * 128 + c4 * 4);
            __half2 a = __floats2half2_rn(v.x, v.y);
            __half2 b = __floats2half2_rn(v.z, v.w);
            uint2 o;
            o.x = *(unsigned int*)&a;
            o.y = *(unsigned int*)&b;
            *(uint2*)&As[r][c4 * 4] = o;
        }
    }, W, C, nRows);
}

// ---------------- CSR gather (fp16 in, fp16 out, fused relu) ----------------
__device__ __forceinline__ float4 h4conv(uint2 v) {
    __half2 a = *(__half2*)&v.x;
    __half2 b = *(__half2*)&v.y;
    float2 fa = __half22float2(a);
    float2 fb = __half22float2(b);
    return make_float4(fa.x, fa.y, fb.x, fb.y);
}

__global__ void __launch_bounds__(256) k_gather(const __half* __restrict__ h,
                                                __half* __restrict__ out,
                                                int doRelu) {
    int warp = (blockIdx.x * blockDim.x + threadIdx.x) >> 5;
    int lane = threadIdx.x & 31;
    if (warp >= NN) return;
    int n = warp;

    const uint2* h2 = (const uint2*)h;
    float di = g_dinv[n];
    float sw = di * di;
    float4 hv = h4conv(h2[(size_t)n * 32 + lane]);
    float4 acc = make_float4(hv.x * sw, hv.y * sw, hv.z * sw, hv.w * sw);

    int i   = g_rowstart[n];
    int end = g_rowstart[n + 1];
    for (; i + 3 < end; i += 4) {
        int2 e0 = g_csr[i], e1 = g_csr[i + 1], e2 = g_csr[i + 2], e3 = g_csr[i + 3];
        float4 v0 = h4conv(h2[(size_t)e0.x * 32 + lane]);
        float4 v1 = h4conv(h2[(size_t)e1.x * 32 + lane]);
        float4 v2 = h4conv(h2[(size_t)e2.x * 32 + lane]);
        float4 v3 = h4conv(h2[(size_t)e3.x * 32 + lane]);
        float w0 = __int_as_float(e0.y), w1 = __int_as_float(e1.y);
        float w2 = __int_as_float(e2.y), w3 = __int_as_float(e3.y);
        acc.x += w0 * v0.x + w1 * v1.x + w2 * v2.x + w3 * v3.x;
        acc.y += w0 * v0.y + w1 * v1.y + w2 * v2.y + w3 * v3.y;
        acc.z += w0 * v0.z + w1 * v1.z + w2 * v2.z + w3 * v3.z;
        acc.w += w0 * v0.w + w1 * v1.w + w2 * v2.w + w3 * v3.w;
    }
    for (; i < end; i++) {
        int2 e0 = g_csr[i];
        float w0 = __int_as_float(e0.y);
        float4 v0 = h4conv(h2[(size_t)e0.x * 32 + lane]);
        acc.x += w0 * v0.x; acc.y += w0 * v0.y;
        acc.z += w0 * v0.z; acc.w += w0 * v0.w;
    }
    if (doRelu) {
        acc.x = fmaxf(acc.x, 0.f); acc.y = fmaxf(acc.y, 0.f);
        acc.z = fmaxf(acc.z, 0.f); acc.w = fmaxf(acc.w, 0.f);
    }
    __half2 p0 = __floats2half2_rn(acc.x, acc.y);
    __half2 p1 = __floats2half2_rn(acc.z, acc.w);
    uint2 o;
    o.x = *(unsigned int*)&p0;
    o.y = *(unsigned int*)&p1;
    ((uint2*)out)[(size_t)n * 32 + lane] = o;
}

// ---------------- pooling (fp16 in) -----------------------------------------
__global__ void __launch_bounds__(128) k_pool(const __half* __restrict__ h) {
    int d = threadIdx.x;
    int n0 = blockIdx.x * 256;
    int n1 = n0 + 256; if (n1 > NN) n1 = NN;
    if (n0 >= NN) return;
    float acc = 0.0f;
    int g = g_batch[n0];
    for (int n = n0; n < n1; n++) {
        int b = g_batch[n];
        if (b != g) {
            atomicAdd(&g_pooled[g * HH + d], acc);
            acc = 0.0f;
            g = b;
        }
        acc += __half2float(h[(size_t)n * HH + d]);
    }
    atomicAdd(&g_pooled[g * HH + d], acc);
}

// ---------------- final MLP (single block) ----------------------------------
__global__ void __launch_bounds__(256) k_mlp(const float* __restrict__ M0w,
                                             const float* __restrict__ M0b,
                                             const float* __restrict__ M1w,
                                             const float* __restrict__ M1b,
                                             float* __restrict__ out) {
    __shared__ float pv[GG * HH];
    int t = threadIdx.x;
    for (int i = t; i < GG * HH; i += 256) {
        int g = i >> 7;
        pv[i] = g_pooled[i] / fmaxf(g_cnts[g], 1.0f);
    }
    __syncthreads();
    float hid[32];
#pragma unroll
    for (int i = 0; i < 32; i++) {
        int idx = t + 256 * i;
        int g = idx >> 7, j = idx & 127;
        float s = M0b[j];
        for (int k = 0; k < 128; k++) s += pv[(g << 7) + k] * M0w[k * 128 + j];
        hid[i] = fmaxf(s, 0.0f);
    }
    __syncthreads();
#pragma unroll
    for (int i = 0; i < 32; i++) pv[t + 256 * i] = hid[i];
    __syncthreads();
    for (int o = t; o < GG * OUTD; o += 256) {
        int g = o / OUTD, c = o % OUTD;
        float s = M1b[c];
        for (int j = 0; j < 128; j++) s += pv[(g << 7) + j] * M1w[j * OUTD + c];
        out[o] = s;
    }
}

// ---------------- launch ----------------------------------------------------
extern "C" void kernel_launch(void* const* d_in, const int* in_sizes, int n_in,
                              void* d_out, int out_size) {
    const float* x   = (const float*)d_in[0];
    const float* W0  = (const float*)d_in[1];
    const float* W1  = (const float*)d_in[2];
    const float* W2  = (const float*)d_in[3];
    const float* M0w = (const float*)d_in[4];
    const float* M0b = (const float*)d_in[5];
    const float* M1w = (const float*)d_in[6];
    const float* M1b = (const float*)d_in[7];
    const void*  ei  = d_in[8];
    const void*  bat = d_in[9];
    float* out = (float*)d_out;

    __half* hA = nullptr;
    __half* hB = nullptr;
    __half* w16 = nullptr;
    cudaGetSymbolAddress((void**)&hA, g_h16a);
    cudaGetSymbolAddress((void**)&hB, g_h16b);
    cudaGetSymbolAddress((void**)&w16, g_w16);

    const int T = 256;
    int gN = (NN + T - 1) / T;              // 196
    int gE = (EE + T - 1) / T;              // 3125
    int gGemm   = (NN + 127) / 128;         // 391
    int gGather = (NN * 32 + T - 1) / T;    // 6250
    int gW      = (3 * HH * HH / 4 + T - 1) / T;   // 48

    // order chosen so the profiled launch (index 3) is the layer-1 GEMM
    k_zero<<<gN, T>>>();                            // 0
    k_cvtw<<<gW, T>>>(W0, W1, W2);                  // 1
    k_detect<<<1, 256>>>((const int*)ei);           // 2
    k_gemm_f32in<<<gGemm, T>>>(x, w16, hB, NN);     // 3  <- profiled
    k_cvt_edges<<<gE, T>>>(ei);                     // 4
    k_cvt_batch<<<gN, T>>>(bat);                    // 5
    k_scan<<<1, 1024>>>();                          // 6
    k_fill<<<gE, T>>>();                            // 7

    k_gather<<<gGather, T>>>(hB, hA, 1);            // layer 1 agg + relu
    k_gemm<<<gGemm, T>>>(hA, w16 + HH * HH, hB, NN);
    k_gather<<<gGather, T>>>(hB, hA, 1);            // layer 2
    k_gemm<<<gGemm, T>>>(hA, w16 + 2 * HH * HH, hB, NN);
    k_gather<<<gGather, T>>>(hB, hA, 0);            // layer 3 (no relu)

    k_pool<<<(NN + 255) / 256, 128>>>(hA);
    k_mlp<<<1, 256>>>(M0w, M0b, M1w, M1b, out);
}

// round 6
// speedup vs baseline: 1.2108x; 1.1524x over previous
#include <cuda_runtime.h>
#include <cuda_fp16.h>
#include <mma.h>
#include <cstdint>

using namespace nvcuda;

#define NN   50000
#define PADN 50176
#define EE   800000
#define HH   128
#define GG   64
#define OUTD 10

// ---------------- scratch (device globals; no dynamic allocation) ----------
__device__ __half g_h16a[(size_t)PADN * HH];  // gemm input / gather output
__device__ __half g_h16b[(size_t)PADN * HH];  // gemm output / gather input
__device__ __half g_w16[3 * HH * HH];         // fp16 weights
__device__ int    g_src[EE];
__device__ int    g_dst[EE];
__device__ int    g_batch[NN];
__device__ int    g_deg[NN];
__device__ int    g_rowstart[NN + 1];
__device__ int    g_cursor[NN];
__device__ float  g_dinv[NN];
__device__ int2   g_csr[EE];                  // packed (src, w-as-int)
__device__ float  g_pooled[GG * HH];
__device__ float  g_cnts[GG];
__device__ int    g_is64;

// ---------------- setup -----------------------------------------------------
__global__ void k_zero() {
    int i = blockIdx.x * blockDim.x + threadIdx.x;
    if (i < NN) g_deg[i] = 0;
    if (i < GG * HH) g_pooled[i] = 0.0f;
    if (i < GG) g_cnts[i] = 0.0f;
}

// weights-only fp32 -> fp16
__global__ void k_cvtw(const float* __restrict__ W0,
                       const float* __restrict__ W1,
                       const float* __restrict__ W2) {
    const int WQ = HH * HH / 4;          // 4096
    int i = blockIdx.x * blockDim.x + threadIdx.x;
    if (i >= 3 * WQ) return;
    const float4* src;
    int off;
    if (i < WQ)          { src = (const float4*)W0; off = i; }
    else if (i < 2 * WQ) { src = (const float4*)W1; off = i - WQ; }
    else                 { src = (const float4*)W2; off = i - 2 * WQ; }
    float4 v = src[off];
    __half2 a = __floats2half2_rn(v.x, v.y);
    __half2 b = __floats2half2_rn(v.z, v.w);
    uint2 o;
    o.x = *(unsigned int*)&a;
    o.y = *(unsigned int*)&b;
    ((uint2*)g_w16)[i] = o;
}

__global__ void k_detect(const int* __restrict__ p) {
    __shared__ int any;
    if (threadIdx.x == 0) any = 0;
    __syncthreads();
    int v = 0;
    for (int i = threadIdx.x; i < 4096; i += blockDim.x) v |= p[2 * i + 1];
    if (v) atomicOr(&any, 1);
    __syncthreads();
    if (threadIdx.x == 0) g_is64 = any ? 0 : 1;
}

// convert edges to int32 AND build degree histogram in one pass
__global__ void k_cvt_edges(const void* __restrict__ p) {
    int e = blockIdx.x * blockDim.x + threadIdx.x;
    if (e >= EE) return;
    int s, d;
    if (g_is64) {
        const long long* q = (const long long*)p;
        s = (int)q[e];
        d = (int)q[EE + e];
    } else {
        const int* q = (const int*)p;
        s = q[e];
        d = q[EE + e];
    }
    s = min(max(s, 0), NN - 1);
    d = min(max(d, 0), NN - 1);
    g_src[e] = s;
    g_dst[e] = d;
    atomicAdd(&g_deg[d], 1);
}

// convert batch AND count nodes-per-graph, warp-aggregated
__global__ void k_cvt_batch(const void* __restrict__ p) {
    int n = blockIdx.x * blockDim.x + threadIdx.x;
    if (n >= NN) return;
    int b;
    if (g_is64) b = (int)((const long long*)p)[n];
    else        b = ((const int*)p)[n];
    b = min(max(b, 0), GG - 1);
    g_batch[n] = b;
    unsigned am = __activemask();
    unsigned mask = __match_any_sync(am, b);
    int leader = __ffs(mask) - 1;
    if ((threadIdx.x & 31) == leader)
        atomicAdd(&g_cnts[b], (float)__popc(mask));
}

// single-block scan of g_deg -> g_rowstart; also emits cursor + dinv
__global__ void k_scan() {
    __shared__ int part[1024];
    const int CHUNK = 49;
    int t = threadIdx.x;
    int base = t * CHUNK;
    int s = 0;
    for (int i = 0; i < CHUNK; i++) {
        int idx = base + i;
        if (idx < NN) s += g_deg[idx];
    }
    part[t] = s;
    __syncthreads();
    for (int off = 1; off < 1024; off <<= 1) {
        int v = (t >= off) ? part[t - off] : 0;
        __syncthreads();
        part[t] += v;
        __syncthreads();
    }
    int run = (t == 0) ? 0 : part[t - 1];
    for (int i = 0; i < CHUNK; i++) {
        int idx = base + i;
        if (idx <= NN) {
            g_rowstart[idx] = run;
            if (idx < NN) {
                int dg = g_deg[idx];
                g_cursor[idx] = run;
                g_dinv[idx] = rsqrtf((float)dg + 1.0f);
                run += dg;
            }
        }
    }
}

__global__ void k_fill() {
    int e = blockIdx.x * blockDim.x + threadIdx.x;
    if (e < EE) {
        int s = g_src[e];
        int d = g_dst[e];
        float w = g_dinv[s] * g_dinv[d];
        int pos = atomicAdd(&g_cursor[d], 1);
        g_csr[pos] = make_int2(s, __float_as_int(w));
    }
}

// ---------------- tensor-core GEMM -------------------------------------------
// block 256 thr (8 warps), tile 128x128, full K=128 in smem. W cached in smem.
// Epilogue: fp32 accum -> fp16 fragment in registers -> direct global store.
#define LDA 136
#define SMEM_GEMM (2 * 128 * LDA * (int)sizeof(__half))   // 69,632 B

template <typename LOADA>
__device__ __forceinline__ void gemm_body(LOADA loadA,
                                          const __half* __restrict__ W,
                                          __half* __restrict__ C,
                                          int nRows) {
    extern __shared__ __half sm[];
    __half* As = sm;                   // 128 x LDA
    __half* Ws = sm + 128 * LDA;       // 128 x LDA

    int tid  = threadIdx.x;
    int w    = tid >> 5;
    int row0 = blockIdx.x * 128;

    loadA(As, row0, tid, nRows);
    // load W (128x128 halves = 2048 uint4), 8 per thread
#pragma unroll
    for (int i = 0; i < 8; i++) {
        int idx = tid + i * 256;
        int r  = idx >> 4;
        int c8 = idx & 15;
        uint4 v = *(const uint4*)(W + r * 128 + c8 * 8);
        *(uint4*)(Ws + r * LDA + c8 * 8) = v;
    }
    __syncthreads();

    int wr = w >> 1, wc = w & 1;
    int r0w = wr * 32, c0w = wc * 64;

    wmma::fragment<wmma::accumulator, 16, 16, 16, float> c[2][4];
#pragma unroll
    for (int i = 0; i < 2; i++)
#pragma unroll
        for (int j = 0; j < 4; j++) wmma::fill_fragment(c[i][j], 0.0f);

#pragma unroll
    for (int k0 = 0; k0 < 128; k0 += 16) {
        wmma::fragment<wmma::matrix_a, 16, 16, 16, __half, wmma::row_major> a[2];
        wmma::fragment<wmma::matrix_b, 16, 16, 16, __half, wmma::row_major> b[4];
#pragma unroll
        for (int i = 0; i < 2; i++)
            wmma::load_matrix_sync(a[i], As + (r0w + i * 16) * LDA + k0, LDA);
#pragma unroll
        for (int j = 0; j < 4; j++)
            wmma::load_matrix_sync(b[j], Ws + k0 * LDA + c0w + j * 16, LDA);
#pragma unroll
        for (int i = 0; i < 2; i++)
#pragma unroll
            for (int j = 0; j < 4; j++)
                wmma::mma_sync(c[i][j], a[i], b[j], c[i][j]);
    }

    // register epilogue: convert to half fragment, store direct to global.
    // C buffers are padded to PADN rows, so tail-block stores are safe.
#pragma unroll
    for (int i = 0; i < 2; i++) {
#pragma unroll
        for (int j = 0; j < 4; j++) {
            wmma::fragment<wmma::accumulator, 16, 16, 16, __half> hc;
#pragma unroll
            for (int e = 0; e < hc.num_elements; e++)
                hc.x[e] = __float2half(c[i][j].x[e]);
            wmma::store_matrix_sync(C + (size_t)(row0 + r0w + i * 16) * 128 + c0w + j * 16,
                                    hc, 128, wmma::mem_row_major);
        }
    }
}

// fp16-A GEMM (layers 2, 3)
__global__ void __launch_bounds__(256) k_gemm(const __half* __restrict__ A,
                                              const __half* __restrict__ W,
                                              __half* __restrict__ C,
                                              int nRows) {
    gemm_body([A](__half* As, int row0, int tid, int nR) {
#pragma unroll
        for (int i = 0; i < 8; i++) {
            int idx = tid + i * 256;
            int r  = idx >> 4;
            int c8 = idx & 15;
            uint4 v = make_uint4(0u, 0u, 0u, 0u);
            if (row0 + r < nR)
                v = *(const uint4*)(A + (size_t)(row0 + r) * 128 + c8 * 8);
            *(uint4*)(As + r * LDA + c8 * 8) = v;
        }
    }, W, C, nRows);
}

// fp32-A GEMM (layer 1: reads x directly, converts in smem-load phase)
__global__ void __launch_bounds__(256) k_gemm_f32in(const float* __restrict__ A,
                                                    const __half* __restrict__ W,
                                                    __half* __restrict__ C,
                                                    int nRows) {
    gemm_body([A](__half* As, int row0, int tid, int nR) {
#pragma unroll
        for (int i = 0; i < 16; i++) {
            int idx = tid + i * 256;      // 0..4095 float4s
            int r  = idx >> 5;
            int c4 = idx & 31;
            float4 v = make_float4(0.f, 0.f, 0.f, 0.f);
            if (row0 + r < nR)
                v = *(const float4*)(A + (size_t)(row0 + r) * 128 + c4 * 4);
            __half2 a = __floats2half2_rn(v.x, v.y);
            __half2 b = __floats2half2_rn(v.z, v.w);
            uint2 o;
            o.x = *(unsigned int*)&a;
            o.y = *(unsigned int*)&b;
            *(uint2*)(As + r * LDA + c4 * 4) = o;
        }
    }, W, C, nRows);
}

// ---------------- CSR gather (fp16 in, fp16 out, fused relu) ----------------
__device__ __forceinline__ float4 h4conv(uint2 v) {
    __half2 a = *(__half2*)&v.x;
    __half2 b = *(__half2*)&v.y;
    float2 fa = __half22float2(a);
    float2 fb = __half22float2(b);
    return make_float4(fa.x, fa.y, fb.x, fb.y);
}

__global__ void __launch_bounds__(256) k_gather(const __half* __restrict__ h,
                                                __half* __restrict__ out,
                                                int doRelu) {
    int warp = (blockIdx.x * blockDim.x + threadIdx.x) >> 5;
    int lane = threadIdx.x & 31;
    if (warp >= NN) return;
    int n = warp;

    const uint2* h2 = (const uint2*)h;
    float di = g_dinv[n];
    float sw = di * di;
    float4 hv = h4conv(h2[(size_t)n * 32 + lane]);
    float4 acc = make_float4(hv.x * sw, hv.y * sw, hv.z * sw, hv.w * sw);

    int i   = g_rowstart[n];
    int end = g_rowstart[n + 1];
    for (; i + 3 < end; i += 4) {
        int2 e0 = g_csr[i], e1 = g_csr[i + 1], e2 = g_csr[i + 2], e3 = g_csr[i + 3];
        float4 v0 = h4conv(h2[(size_t)e0.x * 32 + lane]);
        float4 v1 = h4conv(h2[(size_t)e1.x * 32 + lane]);
        float4 v2 = h4conv(h2[(size_t)e2.x * 32 + lane]);
        float4 v3 = h4conv(h2[(size_t)e3.x * 32 + lane]);
        float w0 = __int_as_float(e0.y), w1 = __int_as_float(e1.y);
        float w2 = __int_as_float(e2.y), w3 = __int_as_float(e3.y);
        acc.x += w0 * v0.x + w1 * v1.x + w2 * v2.x + w3 * v3.x;
        acc.y += w0 * v0.y + w1 * v1.y + w2 * v2.y + w3 * v3.y;
        acc.z += w0 * v0.z + w1 * v1.z + w2 * v2.z + w3 * v3.z;
        acc.w += w0 * v0.w + w1 * v1.w + w2 * v2.w + w3 * v3.w;
    }
    for (; i < end; i++) {
        int2 e0 = g_csr[i];
        float w0 = __int_as_float(e0.y);
        float4 v0 = h4conv(h2[(size_t)e0.x * 32 + lane]);
        acc.x += w0 * v0.x; acc.y += w0 * v0.y;
        acc.z += w0 * v0.z; acc.w += w0 * v0.w;
    }
    if (doRelu) {
        acc.x = fmaxf(acc.x, 0.f); acc.y = fmaxf(acc.y, 0.f);
        acc.z = fmaxf(acc.z, 0.f); acc.w = fmaxf(acc.w, 0.f);
    }
    __half2 p0 = __floats2half2_rn(acc.x, acc.y);
    __half2 p1 = __floats2half2_rn(acc.z, acc.w);
    uint2 o;
    o.x = *(unsigned int*)&p0;
    o.y = *(unsigned int*)&p1;
    ((uint2*)out)[(size_t)n * 32 + lane] = o;
}

// ---------------- pooling (fp16 in) -----------------------------------------
__global__ void __launch_bounds__(128) k_pool(const __half* __restrict__ h) {
    int d = threadIdx.x;
    int n0 = blockIdx.x * 256;
    int n1 = n0 + 256; if (n1 > NN) n1 = NN;
    if (n0 >= NN) return;
    float acc = 0.0f;
    int g = g_batch[n0];
    for (int n = n0; n < n1; n++) {
        int b = g_batch[n];
        if (b != g) {
            atomicAdd(&g_pooled[g * HH + d], acc);
            acc = 0.0f;
            g = b;
        }
        acc += __half2float(h[(size_t)n * HH + d]);
    }
    atomicAdd(&g_pooled[g * HH + d], acc);
}

// ---------------- final MLP (single block) ----------------------------------
__global__ void __launch_bounds__(256) k_mlp(const float* __restrict__ M0w,
                                             const float* __restrict__ M0b,
                                             const float* __restrict__ M1w,
                                             const float* __restrict__ M1b,
                                             float* __restrict__ out) {
    __shared__ float pv[GG * HH];
    int t = threadIdx.x;
    for (int i = t; i < GG * HH; i += 256) {
        int g = i >> 7;
        pv[i] = g_pooled[i] / fmaxf(g_cnts[g], 1.0f);
    }
    __syncthreads();
    float hid[32];
#pragma unroll
    for (int i = 0; i < 32; i++) {
        int idx = t + 256 * i;
        int g = idx >> 7, j = idx & 127;
        float s = M0b[j];
        for (int k = 0; k < 128; k++) s += pv[(g << 7) + k] * M0w[k * 128 + j];
        hid[i] = fmaxf(s, 0.0f);
    }
    __syncthreads();
#pragma unroll
    for (int i = 0; i < 32; i++) pv[t + 256 * i] = hid[i];
    __syncthreads();
    for (int o = t; o < GG * OUTD; o += 256) {
        int g = o / OUTD, c = o % OUTD;
        float s = M1b[c];
        for (int j = 0; j < 128; j++) s += pv[(g << 7) + j] * M1w[j * OUTD + c];
        out[o] = s;
    }
}

// ---------------- launch ----------------------------------------------------
extern "C" void kernel_launch(void* const* d_in, const int* in_sizes, int n_in,
                              void* d_out, int out_size) {
    const float* x   = (const float*)d_in[0];
    const float* W0  = (const float*)d_in[1];
    const float* W1  = (const float*)d_in[2];
    const float* W2  = (const float*)d_in[3];
    const float* M0w = (const float*)d_in[4];
    const float* M0b = (const float*)d_in[5];
    const float* M1w = (const float*)d_in[6];
    const float* M1b = (const float*)d_in[7];
    const void*  ei  = d_in[8];
    const void*  bat = d_in[9];
    float* out = (float*)d_out;

    __half* hA = nullptr;
    __half* hB = nullptr;
    __half* w16 = nullptr;
    cudaGetSymbolAddress((void**)&hA, g_h16a);
    cudaGetSymbolAddress((void**)&hB, g_h16b);
    cudaGetSymbolAddress((void**)&w16, g_w16);

    static int attr_done = 0;
    if (!attr_done) {
        cudaFuncSetAttribute(k_gemm, cudaFuncAttributeMaxDynamicSharedMemorySize, SMEM_GEMM);
        cudaFuncSetAttribute(k_gemm_f32in, cudaFuncAttributeMaxDynamicSharedMemorySize, SMEM_GEMM);
        attr_done = 1;
    }

    const int T = 256;
    int gN = (NN + T - 1) / T;              // 196
    int gE = (EE + T - 1) / T;              // 3125
    int gGemm   = (NN + 127) / 128;         // 391
    int gGather = (NN * 32 + T - 1) / T;    // 6250
    int gW      = (3 * HH * HH / 4 + T - 1) / T;   // 48

    // order chosen so the profiled launch (index 3) is the layer-1 GEMM
    k_zero<<<gN, T>>>();                                        // 0
    k_cvtw<<<gW, T>>>(W0, W1, W2);                              // 1
    k_detect<<<1, 256>>>((const int*)ei);                       // 2
    k_gemm_f32in<<<gGemm, T, SMEM_GEMM>>>(x, w16, hB, NN);      // 3  <- profiled
    k_cvt_edges<<<gE, T>>>(ei);                                 // 4
    k_cvt_batch<<<gN, T>>>(bat);                                // 5
    k_scan<<<1, 1024>>>();                                      // 6
    k_fill<<<gE, T>>>();                                        // 7

    k_gather<<<gGather, T>>>(hB, hA, 1);                        // layer 1 agg
    k_gemm<<<gGemm, T, SMEM_GEMM>>>(hA, w16 + HH * HH, hB, NN);
    k_gather<<<gGather, T>>>(hB, hA, 1);                        // layer 2
    k_gemm<<<gGemm, T, SMEM_GEMM>>>(hA, w16 + 2 * HH * HH, hB, NN);
    k_gather<<<gGather, T>>>(hB, hA, 0);                        // layer 3

    k_pool<<<(NN + 255) / 256, 128>>>(hA);
    k_mlp<<<1, 256>>>(M0w, M0b, M1w, M1b, out);
}

// round 7
// speedup vs baseline: 1.2232x; 1.0103x over previous
#include <cuda_runtime.h>
#include <cuda_fp16.h>
#include <mma.h>
#include <cstdint>

using namespace nvcuda;

#define NN   50000
#define PADN 50176
#define EE   800000
#define HH   128
#define GG   64
#define OUTD 10

// ---------------- scratch (device globals; no dynamic allocation) ----------
__device__ __half g_h16a[(size_t)PADN * HH];  // gemm input / gather output
__device__ __half g_h16b[(size_t)PADN * HH];  // gemm output / gather input
__device__ __half g_w16[3 * HH * HH];         // fp16 weights
__device__ int    g_batch[NN];
__device__ int    g_deg[NN];
__device__ int    g_rowstart[NN + 1];
__device__ int    g_cursor[NN];
__device__ float  g_dinv[NN];
__device__ int2   g_csr[EE];                  // packed (src, w-as-int)
__device__ float  g_pooled[GG * HH];
__device__ float  g_cnts[GG];
__device__ int    g_is64;

// ---------------- edge decode helper ----------------------------------------
__device__ __forceinline__ void decode_edge(const void* p, int e, int& s, int& d) {
    if (g_is64) {
        const long long* q = (const long long*)p;
        s = (int)q[e];
        d = (int)q[EE + e];
    } else {
        const int* q = (const int*)p;
        s = q[e];
        d = q[EE + e];
    }
    s = min(max(s, 0), NN - 1);
    d = min(max(d, 0), NN - 1);
}

// ---------------- setup -----------------------------------------------------
__global__ void k_zero() {
    int i = blockIdx.x * blockDim.x + threadIdx.x;
    if (i < NN) g_deg[i] = 0;
    if (i < GG * HH) g_pooled[i] = 0.0f;
    if (i < GG) g_cnts[i] = 0.0f;
}

__global__ void k_cvtw(const float* __restrict__ W0,
                       const float* __restrict__ W1,
                       const float* __restrict__ W2) {
    const int WQ = HH * HH / 4;          // 4096
    int i = blockIdx.x * blockDim.x + threadIdx.x;
    if (i >= 3 * WQ) return;
    const float4* src;
    int off;
    if (i < WQ)          { src = (const float4*)W0; off = i; }
    else if (i < 2 * WQ) { src = (const float4*)W1; off = i - WQ; }
    else                 { src = (const float4*)W2; off = i - 2 * WQ; }
    float4 v = src[off];
    __half2 a = __floats2half2_rn(v.x, v.y);
    __half2 b = __floats2half2_rn(v.z, v.w);
    uint2 o;
    o.x = *(unsigned int*)&a;
    o.y = *(unsigned int*)&b;
    ((uint2*)g_w16)[i] = o;
}

__global__ void k_detect(const int* __restrict__ p) {
    __shared__ int any;
    if (threadIdx.x == 0) any = 0;
    __syncthreads();
    int v = 0;
    for (int i = threadIdx.x; i < 4096; i += blockDim.x) v |= p[2 * i + 1];
    if (v) atomicOr(&any, 1);
    __syncthreads();
    if (threadIdx.x == 0) g_is64 = any ? 0 : 1;
}

// degree histogram straight from edge_index (no scratch src/dst arrays)
__global__ void k_hist(const void* __restrict__ p) {
    int e = blockIdx.x * blockDim.x + threadIdx.x;
    if (e >= EE) return;
    int s, d;
    decode_edge(p, e, s, d);
    atomicAdd(&g_deg[d], 1);
}

// convert batch AND count nodes-per-graph, warp-aggregated
__global__ void k_cvt_batch(const void* __restrict__ p) {
    int n = blockIdx.x * blockDim.x + threadIdx.x;
    if (n >= NN) return;
    int b;
    if (g_is64) b = (int)((const long long*)p)[n];
    else        b = ((const int*)p)[n];
    b = min(max(b, 0), GG - 1);
    g_batch[n] = b;
    unsigned am = __activemask();
    unsigned mask = __match_any_sync(am, b);
    int leader = __ffs(mask) - 1;
    if ((threadIdx.x & 31) == leader)
        atomicAdd(&g_cnts[b], (float)__popc(mask));
}

// single-block scan of g_deg -> g_rowstart; also emits cursor + dinv
__global__ void k_scan() {
    __shared__ int part[1024];
    const int CHUNK = 49;
    int t = threadIdx.x;
    int base = t * CHUNK;
    int s = 0;
    for (int i = 0; i < CHUNK; i++) {
        int idx = base + i;
        if (idx < NN) s += g_deg[idx];
    }
    part[t] = s;
    __syncthreads();
    for (int off = 1; off < 1024; off <<= 1) {
        int v = (t >= off) ? part[t - off] : 0;
        __syncthreads();
        part[t] += v;
        __syncthreads();
    }
    int run = (t == 0) ? 0 : part[t - 1];
    for (int i = 0; i < CHUNK; i++) {
        int idx = base + i;
        if (idx <= NN) {
            g_rowstart[idx] = run;
            if (idx < NN) {
                int dg = g_deg[idx];
                g_cursor[idx] = run;
                g_dinv[idx] = rsqrtf((float)dg + 1.0f);
                run += dg;
            }
        }
    }
}

// re-reads edge_index, places (src, w) into CSR slots
__global__ void k_fill(const void* __restrict__ p) {
    int e = blockIdx.x * blockDim.x + threadIdx.x;
    if (e >= EE) return;
    int s, d;
    decode_edge(p, e, s, d);
    float w = g_dinv[s] * g_dinv[d];
    int pos = atomicAdd(&g_cursor[d], 1);
    g_csr[pos] = make_int2(s, __float_as_int(w));
}

// ---------------- tensor-core GEMM -------------------------------------------
#define LDA 136
#define SMEM_GEMM (2 * 128 * LDA * (int)sizeof(__half))   // 69,632 B

template <typename LOADA>
__device__ __forceinline__ void gemm_body(LOADA loadA,
                                          const __half* __restrict__ W,
                                          __half* __restrict__ C,
                                          int nRows) {
    extern __shared__ __half sm[];
    __half* As = sm;                   // 128 x LDA
    __half* Ws = sm + 128 * LDA;       // 128 x LDA

    int tid  = threadIdx.x;
    int w    = tid >> 5;
    int row0 = blockIdx.x * 128;

    loadA(As, row0, tid, nRows);
#pragma unroll
    for (int i = 0; i < 8; i++) {
        int idx = tid + i * 256;
        int r  = idx >> 4;
        int c8 = idx & 15;
        uint4 v = *(const uint4*)(W + r * 128 + c8 * 8);
        *(uint4*)(Ws + r * LDA + c8 * 8) = v;
    }
    __syncthreads();

    int wr = w >> 1, wc = w & 1;
    int r0w = wr * 32, c0w = wc * 64;

    wmma::fragment<wmma::accumulator, 16, 16, 16, float> c[2][4];
#pragma unroll
    for (int i = 0; i < 2; i++)
#pragma unroll
        for (int j = 0; j < 4; j++) wmma::fill_fragment(c[i][j], 0.0f);

#pragma unroll
    for (int k0 = 0; k0 < 128; k0 += 16) {
        wmma::fragment<wmma::matrix_a, 16, 16, 16, __half, wmma::row_major> a[2];
        wmma::fragment<wmma::matrix_b, 16, 16, 16, __half, wmma::row_major> b[4];
#pragma unroll
        for (int i = 0; i < 2; i++)
            wmma::load_matrix_sync(a[i], As + (r0w + i * 16) * LDA + k0, LDA);
#pragma unroll
        for (int j = 0; j < 4; j++)
            wmma::load_matrix_sync(b[j], Ws + k0 * LDA + c0w + j * 16, LDA);
#pragma unroll
        for (int i = 0; i < 2; i++)
#pragma unroll
            for (int j = 0; j < 4; j++)
                wmma::mma_sync(c[i][j], a[i], b[j], c[i][j]);
    }

    // register epilogue: fp32 accum -> fp16 fragment -> direct global store.
    // C buffers padded to PADN rows, so tail-block stores are safe.
#pragma unroll
    for (int i = 0; i < 2; i++) {
#pragma unroll
        for (int j = 0; j < 4; j++) {
            wmma::fragment<wmma::accumulator, 16, 16, 16, __half> hc;
#pragma unroll
            for (int e = 0; e < hc.num_elements; e++)
                hc.x[e] = __float2half(c[i][j].x[e]);
            wmma::store_matrix_sync(C + (size_t)(row0 + r0w + i * 16) * 128 + c0w + j * 16,
                                    hc, 128, wmma::mem_row_major);
        }
    }
}

__global__ void __launch_bounds__(256) k_gemm(const __half* __restrict__ A,
                                              const __half* __restrict__ W,
                                              __half* __restrict__ C,
                                              int nRows) {
    gemm_body([A](__half* As, int row0, int tid, int nR) {
#pragma unroll
        for (int i = 0; i < 8; i++) {
            int idx = tid + i * 256;
            int r  = idx >> 4;
            int c8 = idx & 15;
            uint4 v = make_uint4(0u, 0u, 0u, 0u);
            if (row0 + r < nR)
                v = *(const uint4*)(A + (size_t)(row0 + r) * 128 + c8 * 8);
            *(uint4*)(As + r * LDA + c8 * 8) = v;
        }
    }, W, C, nRows);
}

__global__ void __launch_bounds__(256) k_gemm_f32in(const float* __restrict__ A,
                                                    const __half* __restrict__ W,
                                                    __half* __restrict__ C,
                                                    int nRows) {
    gemm_body([A](__half* As, int row0, int tid, int nR) {
#pragma unroll
        for (int i = 0; i < 16; i++) {
            int idx = tid + i * 256;
            int r  = idx >> 5;
            int c4 = idx & 31;
            float4 v = make_float4(0.f, 0.f, 0.f, 0.f);
            if (row0 + r < nR)
                v = *(const float4*)(A + (size_t)(row0 + r) * 128 + c4 * 4);
            __half2 a = __floats2half2_rn(v.x, v.y);
            __half2 b = __floats2half2_rn(v.z, v.w);
            uint2 o;
            o.x = *(unsigned int*)&a;
            o.y = *(unsigned int*)&b;
            *(uint2*)(As + r * LDA + c4 * 4) = o;
        }
    }, W, C, nRows);
}

// ---------------- CSR gather: half-warp (16 lanes) per node, uint4 loads ----
__device__ __forceinline__ void unp8(uint4 v, float* f) {
    float2 a = __half22float2(*(__half2*)&v.x);
    float2 b = __half22float2(*(__half2*)&v.y);
    float2 c = __half22float2(*(__half2*)&v.z);
    float2 d = __half22float2(*(__half2*)&v.w);
    f[0] = a.x; f[1] = a.y; f[2] = b.x; f[3] = b.y;
    f[4] = c.x; f[5] = c.y; f[6] = d.x; f[7] = d.y;
}

__global__ void __launch_bounds__(256) k_gather(const __half* __restrict__ h,
                                                __half* __restrict__ out,
                                                int doRelu) {
    int hw   = (blockIdx.x * blockDim.x + threadIdx.x) >> 4;  // half-warp = node
    int lane = threadIdx.x & 15;                              // 16 B per lane
    if (hw >= NN) return;
    int n = hw;

    const uint4* h4 = (const uint4*)h;   // 16 uint4 per 128-half row
    float di = g_dinv[n];
    float sw = di * di;
    float acc[8], f0[8], f1[8];
    unp8(h4[(size_t)n * 16 + lane], acc);
#pragma unroll
    for (int k = 0; k < 8; k++) acc[k] *= sw;

    int i   = g_rowstart[n];
    int end = g_rowstart[n + 1];
    for (; i + 1 < end; i += 2) {
        int2 e0 = g_csr[i];
        int2 e1 = g_csr[i + 1];
        uint4 v0 = h4[(size_t)e0.x * 16 + lane];
        uint4 v1 = h4[(size_t)e1.x * 16 + lane];
        float w0 = __int_as_float(e0.y);
        float w1 = __int_as_float(e1.y);
        unp8(v0, f0);
        unp8(v1, f1);
#pragma unroll
        for (int k = 0; k < 8; k++) acc[k] += w0 * f0[k] + w1 * f1[k];
    }
    if (i < end) {
        int2 e0 = g_csr[i];
        uint4 v0 = h4[(size_t)e0.x * 16 + lane];
        float w0 = __int_as_float(e0.y);
        unp8(v0, f0);
#pragma unroll
        for (int k = 0; k < 8; k++) acc[k] += w0 * f0[k];
    }
    if (doRelu) {
#pragma unroll
        for (int k = 0; k < 8; k++) acc[k] = fmaxf(acc[k], 0.0f);
    }
    __half2 p0 = __floats2half2_rn(acc[0], acc[1]);
    __half2 p1 = __floats2half2_rn(acc[2], acc[3]);
    __half2 p2 = __floats2half2_rn(acc[4], acc[5]);
    __half2 p3 = __floats2half2_rn(acc[6], acc[7]);
    uint4 o;
    o.x = *(unsigned int*)&p0;
    o.y = *(unsigned int*)&p1;
    o.z = *(unsigned int*)&p2;
    o.w = *(unsigned int*)&p3;
    ((uint4*)out)[(size_t)n * 16 + lane] = o;
}

// ---------------- pooling (fp16 in) -----------------------------------------
__global__ void __launch_bounds__(128) k_pool(const __half* __restrict__ h) {
    int d = threadIdx.x;
    int n0 = blockIdx.x * 256;
    int n1 = n0 + 256; if (n1 > NN) n1 = NN;
    if (n0 >= NN) return;
    float acc = 0.0f;
    int g = g_batch[n0];
    for (int n = n0; n < n1; n++) {
        int b = g_batch[n];
        if (b != g) {
            atomicAdd(&g_pooled[g * HH + d], acc);
            acc = 0.0f;
            g = b;
        }
        acc += __half2float(h[(size_t)n * HH + d]);
    }
    atomicAdd(&g_pooled[g * HH + d], acc);
}

// ---------------- final MLP (single block) ----------------------------------
__global__ void __launch_bounds__(256) k_mlp(const float* __restrict__ M0w,
                                             const float* __restrict__ M0b,
                                             const float* __restrict__ M1w,
                                             const float* __restrict__ M1b,
                                             float* __restrict__ out) {
    __shared__ float pv[GG * HH];
    int t = threadIdx.x;
    for (int i = t; i < GG * HH; i += 256) {
        int g = i >> 7;
        pv[i] = g_pooled[i] / fmaxf(g_cnts[g], 1.0f);
    }
    __syncthreads();
    float hid[32];
#pragma unroll
    for (int i = 0; i < 32; i++) {
        int idx = t + 256 * i;
        int g = idx >> 7, j = idx & 127;
        float s = M0b[j];
        for (int k = 0; k < 128; k++) s += pv[(g << 7) + k] * M0w[k * 128 + j];
        hid[i] = fmaxf(s, 0.0f);
    }
    __syncthreads();
#pragma unroll
    for (int i = 0; i < 32; i++) pv[t + 256 * i] = hid[i];
    __syncthreads();
    for (int o = t; o < GG * OUTD; o += 256) {
        int g = o / OUTD, c = o % OUTD;
        float s = M1b[c];
        for (int j = 0; j < 128; j++) s += pv[(g << 7) + j] * M1w[j * OUTD + c];
        out[o] = s;
    }
}

// ---------------- launch ----------------------------------------------------
extern "C" void kernel_launch(void* const* d_in, const int* in_sizes, int n_in,
                              void* d_out, int out_size) {
    const float* x   = (const float*)d_in[0];
    const float* W0  = (const float*)d_in[1];
    const float* W1  = (const float*)d_in[2];
    const float* W2  = (const float*)d_in[3];
    const float* M0w = (const float*)d_in[4];
    const float* M0b = (const float*)d_in[5];
    const float* M1w = (const float*)d_in[6];
    const float* M1b = (const float*)d_in[7];
    const void*  ei  = d_in[8];
    const void*  bat = d_in[9];
    float* out = (float*)d_out;

    __half* hA = nullptr;
    __half* hB = nullptr;
    __half* w16 = nullptr;
    cudaGetSymbolAddress((void**)&hA, g_h16a);
    cudaGetSymbolAddress((void**)&hB, g_h16b);
    cudaGetSymbolAddress((void**)&w16, g_w16);

    static int attr_done = 0;
    if (!attr_done) {
        cudaFuncSetAttribute(k_gemm, cudaFuncAttributeMaxDynamicSharedMemorySize, SMEM_GEMM);
        cudaFuncSetAttribute(k_gemm_f32in, cudaFuncAttributeMaxDynamicSharedMemorySize, SMEM_GEMM);
        attr_done = 1;
    }

    const int T = 256;
    int gN = (NN + T - 1) / T;              // 196
    int gE = (EE + T - 1) / T;              // 3125
    int gGemm   = (NN + 127) / 128;         // 391
    int gGather = (NN * 16 + T - 1) / T;    // 3125
    int gW      = (3 * HH * HH / 4 + T - 1) / T;   // 48

    // profiled launch is index 3 -> k_hist this round
    k_zero<<<gN, T>>>();                                        // 0
    k_cvtw<<<gW, T>>>(W0, W1, W2);                              // 1
    k_detect<<<1, 256>>>((const int*)ei);                       // 2
    k_hist<<<gE, T>>>(ei);                                      // 3  <- profiled
    k_gemm_f32in<<<gGemm, T, SMEM_GEMM>>>(x, w16, hB, NN);      // 4
    k_cvt_batch<<<gN, T>>>(bat);                                // 5
    k_scan<<<1, 1024>>>();                                      // 6
    k_fill<<<gE, T>>>(ei);                                      // 7

    k_gather<<<gGather, T>>>(hB, hA, 1);                        // layer 1 agg
    k_gemm<<<gGemm, T, SMEM_GEMM>>>(hA, w16 + HH * HH, hB, NN);
    k_gather<<<gGather, T>>>(hB, hA, 1);                        // layer 2
    k_gemm<<<gGemm, T, SMEM_GEMM>>>(hA, w16 + 2 * HH * HH, hB, NN);
    k_gather<<<gGather, T>>>(hB, hA, 0);                        // layer 3

    k_pool<<<(NN + 255) / 256, 128>>>(hA);
    k_mlp<<<1, 256>>>(M0w, M0b, M1w, M1b, out);
}

// round 8
// speedup vs baseline: 1.6786x; 1.3723x over previous
#include <cuda_runtime.h>
#include <cuda_fp16.h>
#include <mma.h>
#include <cstdint>

using namespace nvcuda;

#define NN   50000
#define PADN 50176
#define PADDEG 53248
#define EE   800000
#define HH   128
#define GG   64
#define OUTD 10

// ---------------- scratch (device globals; no dynamic allocation) ----------
__device__ __half g_h16a[(size_t)PADN * HH];  // gemm input / gather output
__device__ __half g_h16b[(size_t)PADN * HH];  // gemm output / gather input
__device__ __half g_w16[3 * HH * HH];         // fp16 weights
__device__ int    g_batch[NN];
__device__ int    g_deg[PADDEG];              // padded for int4 scan
__device__ int    g_rowstart[NN + 1];
__device__ int    g_cursor[NN];
__device__ float  g_dinv[NN];
__device__ int    g_csri[EE];                 // src index only
__device__ float  g_pooled[GG * HH];
__device__ float  g_cnts[GG];
__device__ int    g_is64;

// ---------------- edge decode helper ----------------------------------------
__device__ __forceinline__ void decode_edge(const void* p, int e, int& s, int& d) {
    if (g_is64) {
        const long long* q = (const long long*)p;
        s = (int)q[e];
        d = (int)q[EE + e];
    } else {
        const int* q = (const int*)p;
        s = q[e];
        d = q[EE + e];
    }
    s = min(max(s, 0), NN - 1);
    d = min(max(d, 0), NN - 1);
}

// ---------------- setup -----------------------------------------------------
__global__ void k_zero() {
    int i = blockIdx.x * blockDim.x + threadIdx.x;
    if (i < PADDEG) g_deg[i] = 0;
    if (i < GG * HH) g_pooled[i] = 0.0f;
    if (i < GG) g_cnts[i] = 0.0f;
}

__global__ void k_cvtw(const float* __restrict__ W0,
                       const float* __restrict__ W1,
                       const float* __restrict__ W2) {
    const int WQ = HH * HH / 4;          // 4096
    int i = blockIdx.x * blockDim.x + threadIdx.x;
    if (i >= 3 * WQ) return;
    const float4* src;
    int off;
    if (i < WQ)          { src = (const float4*)W0; off = i; }
    else if (i < 2 * WQ) { src = (const float4*)W1; off = i - WQ; }
    else                 { src = (const float4*)W2; off = i - 2 * WQ; }
    float4 v = src[off];
    __half2 a = __floats2half2_rn(v.x, v.y);
    __half2 b = __floats2half2_rn(v.z, v.w);
    uint2 o;
    o.x = *(unsigned int*)&a;
    o.y = *(unsigned int*)&b;
    ((uint2*)g_w16)[i] = o;
}

__global__ void k_detect(const int* __restrict__ p) {
    __shared__ int any;
    if (threadIdx.x == 0) any = 0;
    __syncthreads();
    int v = 0;
    for (int i = threadIdx.x; i < 4096; i += blockDim.x) v |= p[2 * i + 1];
    if (v) atomicOr(&any, 1);
    __syncthreads();
    if (threadIdx.x == 0) g_is64 = any ? 0 : 1;
}

__global__ void k_hist(const void* __restrict__ p) {
    int e = blockIdx.x * blockDim.x + threadIdx.x;
    if (e >= EE) return;
    int s, d;
    decode_edge(p, e, s, d);
    atomicAdd(&g_deg[d], 1);
}

// convert batch AND count nodes-per-graph, warp-aggregated
__global__ void k_cvt_batch(const void* __restrict__ p) {
    int n = blockIdx.x * blockDim.x + threadIdx.x;
    if (n >= NN) return;
    int b;
    if (g_is64) b = (int)((const long long*)p)[n];
    else        b = ((const int*)p)[n];
    b = min(max(b, 0), GG - 1);
    g_batch[n] = b;
    unsigned am = __activemask();
    unsigned mask = __match_any_sync(am, b);
    int leader = __ffs(mask) - 1;
    if ((threadIdx.x & 31) == leader)
        atomicAdd(&g_cnts[b], (float)__popc(mask));
}

// single-block scan of g_deg -> g_rowstart; emits cursor + dinv. int4 loads.
__global__ void k_scan() {
    __shared__ int part[1024];
    const int CHUNK = 52;                 // 1024*52 = 53248 = PADDEG
    int t = threadIdx.x;
    int base = t * CHUNK;
    int s = 0;
    const int4* d4 = (const int4*)g_deg;
#pragma unroll
    for (int i = 0; i < CHUNK / 4; i++) {
        int4 v = d4[base / 4 + i];        // padding is zeroed, safe
        s += v.x + v.y + v.z + v.w;
    }
    part[t] = s;
    __syncthreads();
    for (int off = 1; off < 1024; off <<= 1) {
        int v = (t >= off) ? part[t - off] : 0;
        __syncthreads();
        part[t] += v;
        __syncthreads();
    }
    int run = (t == 0) ? 0 : part[t - 1];
    for (int i = 0; i < CHUNK; i++) {
        int idx = base + i;
        if (idx <= NN) {
            g_rowstart[idx] = run;
            if (idx < NN) {
                int dg = g_deg[idx];
                g_cursor[idx] = run;
                g_dinv[idx] = rsqrtf((float)dg + 1.0f);
                run += dg;
            }
        }
    }
}

// re-reads edge_index, places src into CSR slots (4B per edge)
__global__ void k_fill(const void* __restrict__ p) {
    int e = blockIdx.x * blockDim.x + threadIdx.x;
    if (e >= EE) return;
    int s, d;
    decode_edge(p, e, s, d);
    int pos = atomicAdd(&g_cursor[d], 1);
    g_csri[pos] = s;
}

// ---------------- tensor-core GEMM -------------------------------------------
#define LDA 136
#define SMEM_GEMM (2 * 128 * LDA * (int)sizeof(__half))   // 69,632 B

template <typename LOADA>
__device__ __forceinline__ void gemm_body(LOADA loadA,
                                          const __half* __restrict__ W,
                                          __half* __restrict__ C,
                                          int nRows) {
    extern __shared__ __half sm[];
    __half* As = sm;                   // 128 x LDA
    __half* Ws = sm + 128 * LDA;       // 128 x LDA

    int tid  = threadIdx.x;
    int w    = tid >> 5;
    int row0 = blockIdx.x * 128;

    loadA(As, row0, tid, nRows);
#pragma unroll
    for (int i = 0; i < 8; i++) {
        int idx = tid + i * 256;
        int r  = idx >> 4;
        int c8 = idx & 15;
        uint4 v = *(const uint4*)(W + r * 128 + c8 * 8);
        *(uint4*)(Ws + r * LDA + c8 * 8) = v;
    }
    __syncthreads();

    int wr = w >> 1, wc = w & 1;
    int r0w = wr * 32, c0w = wc * 64;

    wmma::fragment<wmma::accumulator, 16, 16, 16, float> c[2][4];
#pragma unroll
    for (int i = 0; i < 2; i++)
#pragma unroll
        for (int j = 0; j < 4; j++) wmma::fill_fragment(c[i][j], 0.0f);

#pragma unroll
    for (int k0 = 0; k0 < 128; k0 += 16) {
        wmma::fragment<wmma::matrix_a, 16, 16, 16, __half, wmma::row_major> a[2];
        wmma::fragment<wmma::matrix_b, 16, 16, 16, __half, wmma::row_major> b[4];
#pragma unroll
        for (int i = 0; i < 2; i++)
            wmma::load_matrix_sync(a[i], As + (r0w + i * 16) * LDA + k0, LDA);
#pragma unroll
        for (int j = 0; j < 4; j++)
            wmma::load_matrix_sync(b[j], Ws + k0 * LDA + c0w + j * 16, LDA);
#pragma unroll
        for (int i = 0; i < 2; i++)
#pragma unroll
            for (int j = 0; j < 4; j++)
                wmma::mma_sync(c[i][j], a[i], b[j], c[i][j]);
    }

    // register epilogue: fp32 accum -> fp16 fragment -> direct global store.
#pragma unroll
    for (int i = 0; i < 2; i++) {
#pragma unroll
        for (int j = 0; j < 4; j++) {
            wmma::fragment<wmma::accumulator, 16, 16, 16, __half> hc;
#pragma unroll
            for (int e = 0; e < hc.num_elements; e++)
                hc.x[e] = __float2half(c[i][j].x[e]);
            wmma::store_matrix_sync(C + (size_t)(row0 + r0w + i * 16) * 128 + c0w + j * 16,
                                    hc, 128, wmma::mem_row_major);
        }
    }
}

__global__ void __launch_bounds__(256) k_gemm(const __half* __restrict__ A,
                                              const __half* __restrict__ W,
                                              __half* __restrict__ C,
                                              int nRows) {
    gemm_body([A](__half* As, int row0, int tid, int nR) {
#pragma unroll
        for (int i = 0; i < 8; i++) {
            int idx = tid + i * 256;
            int r  = idx >> 4;
            int c8 = idx & 15;
            uint4 v = make_uint4(0u, 0u, 0u, 0u);
            if (row0 + r < nR)
                v = *(const uint4*)(A + (size_t)(row0 + r) * 128 + c8 * 8);
            *(uint4*)(As + r * LDA + c8 * 8) = v;
        }
    }, W, C, nRows);
}

__global__ void __launch_bounds__(256) k_gemm_f32in(const float* __restrict__ A,
                                                    const __half* __restrict__ W,
                                                    __half* __restrict__ C,
                                                    int nRows) {
    gemm_body([A](__half* As, int row0, int tid, int nR) {
#pragma unroll
        for (int i = 0; i < 16; i++) {
            int idx = tid + i * 256;
            int r  = idx >> 5;
            int c4 = idx & 31;
            float4 v = make_float4(0.f, 0.f, 0.f, 0.f);
            if (row0 + r < nR)
                v = *(const float4*)(A + (size_t)(row0 + r) * 128 + c4 * 4);
            __half2 a = __floats2half2_rn(v.x, v.y);
            __half2 b = __floats2half2_rn(v.z, v.w);
            uint2 o;
            o.x = *(unsigned int*)&a;
            o.y = *(unsigned int*)&b;
            *(uint2*)(As + r * LDA + c4 * 4) = o;
        }
    }, W, C, nRows);
}

// ---------------- CSR gather: half-warp per node, src-only CSR --------------
// out[n] = dinv[n] * ( sum_s dinv[s]*h[s] + dinv[n]*h[n] )
__device__ __forceinline__ void unp8(uint4 v, float* f) {
    float2 a = __half22float2(*(__half2*)&v.x);
    float2 b = __half22float2(*(__half2*)&v.y);
    float2 c = __half22float2(*(__half2*)&v.z);
    float2 d = __half22float2(*(__half2*)&v.w);
    f[0] = a.x; f[1] = a.y; f[2] = b.x; f[3] = b.y;
    f[4] = c.x; f[5] = c.y; f[6] = d.x; f[7] = d.y;
}

__global__ void __launch_bounds__(256) k_gather(const __half* __restrict__ h,
                                                __half* __restrict__ out,
                                                int doRelu) {
    int hw   = (blockIdx.x * blockDim.x + threadIdx.x) >> 4;
    int lane = threadIdx.x & 15;
    if (hw >= NN) return;
    int n = hw;

    const uint4* h4 = (const uint4*)h;
    float di = g_dinv[n];
    float acc[8], f0[8], f1[8], f2[8], f3[8];
    unp8(h4[(size_t)n * 16 + lane], acc);
#pragma unroll
    for (int k = 0; k < 8; k++) acc[k] *= di;   // self term: di*h[n]

    int i   = g_rowstart[n];
    int end = g_rowstart[n + 1];
    for (; i + 3 < end; i += 4) {
        int s0 = g_csri[i],     s1 = g_csri[i + 1];
        int s2 = g_csri[i + 2], s3 = g_csri[i + 3];
        float w0 = __ldg(&g_dinv[s0]), w1 = __ldg(&g_dinv[s1]);
        float w2 = __ldg(&g_dinv[s2]), w3 = __ldg(&g_dinv[s3]);
        uint4 v0 = h4[(size_t)s0 * 16 + lane];
        uint4 v1 = h4[(size_t)s1 * 16 + lane];
        uint4 v2 = h4[(size_t)s2 * 16 + lane];
        uint4 v3 = h4[(size_t)s3 * 16 + lane];
        unp8(v0, f0); unp8(v1, f1); unp8(v2, f2); unp8(v3, f3);
#pragma unroll
        for (int k = 0; k < 8; k++)
            acc[k] += w0 * f0[k] + w1 * f1[k] + w2 * f2[k] + w3 * f3[k];
    }
    for (; i < end; i++) {
        int s0 = g_csri[i];
        float w0 = __ldg(&g_dinv[s0]);
        uint4 v0 = h4[(size_t)s0 * 16 + lane];
        unp8(v0, f0);
#pragma unroll
        for (int k = 0; k < 8; k++) acc[k] += w0 * f0[k];
    }
#pragma unroll
    for (int k = 0; k < 8; k++) acc[k] *= di;
    if (doRelu) {
#pragma unroll
        for (int k = 0; k < 8; k++) acc[k] = fmaxf(acc[k], 0.0f);
    }
    __half2 p0 = __floats2half2_rn(acc[0], acc[1]);
    __half2 p1 = __floats2half2_rn(acc[2], acc[3]);
    __half2 p2 = __floats2half2_rn(acc[4], acc[5]);
    __half2 p3 = __floats2half2_rn(acc[6], acc[7]);
    uint4 o;
    o.x = *(unsigned int*)&p0;
    o.y = *(unsigned int*)&p1;
    o.z = *(unsigned int*)&p2;
    o.w = *(unsigned int*)&p3;
    ((uint4*)out)[(size_t)n * 16 + lane] = o;
}

// ---------------- pooling: warp per 64-node chunk, uint2 loads ---------------
__global__ void __launch_bounds__(128) k_pool(const __half* __restrict__ h) {
    int warp = threadIdx.x >> 5;
    int lane = threadIdx.x & 31;
    int n0 = blockIdx.x * 256 + warp * 64;
    if (n0 >= NN) return;
    int n1 = n0 + 64; if (n1 > NN) n1 = NN;

    const uint2* h2 = (const uint2*)h;   // 32 uint2 per row; lane owns 4 feats
    float a0 = 0.f, a1 = 0.f, a2 = 0.f, a3 = 0.f;
    int g = g_batch[n0];
    for (int n = n0; n < n1; n++) {
        int b = g_batch[n];
        if (b != g) {
            int base = g * HH + lane * 4;
            atomicAdd(&g_pooled[base + 0], a0);
            atomicAdd(&g_pooled[base + 1], a1);
            atomicAdd(&g_pooled[base + 2], a2);
            atomicAdd(&g_pooled[base + 3], a3);
            a0 = a1 = a2 = a3 = 0.f;
            g = b;
        }
        uint2 v = h2[(size_t)n * 32 + lane];
        float2 x = __half22float2(*(__half2*)&v.x);
        float2 y = __half22float2(*(__half2*)&v.y);
        a0 += x.x; a1 += x.y; a2 += y.x; a3 += y.y;
    }
    int base = g * HH + lane * 4;
    atomicAdd(&g_pooled[base + 0], a0);
    atomicAdd(&g_pooled[base + 1], a1);
    atomicAdd(&g_pooled[base + 2], a2);
    atomicAdd(&g_pooled[base + 3], a3);
}

// ---------------- final MLP: one block per graph -----------------------------
__global__ void __launch_bounds__(128) k_mlp(const float* __restrict__ M0w,
                                             const float* __restrict__ M0b,
                                             const float* __restrict__ M1w,
                                             const float* __restrict__ M1b,
                                             float* __restrict__ out) {
    __shared__ float pv[HH];
    __shared__ float hid[HH];
    int g = blockIdx.x;
    int t = threadIdx.x;
    pv[t] = g_pooled[g * HH + t] / fmaxf(g_cnts[g], 1.0f);
    __syncthreads();
    float s = M0b[t];
#pragma unroll 8
    for (int k = 0; k < HH; k++) s += pv[k] * M0w[k * HH + t];
    hid[t] = fmaxf(s, 0.0f);
    __syncthreads();
    if (t < OUTD) {
        float s2 = M1b[t];
#pragma unroll 8
        for (int j = 0; j < HH; j++) s2 += hid[j] * M1w[j * OUTD + t];
        out[g * OUTD + t] = s2;
    }
}

// ---------------- launch ----------------------------------------------------
extern "C" void kernel_launch(void* const* d_in, const int* in_sizes, int n_in,
                              void* d_out, int out_size) {
    const float* x   = (const float*)d_in[0];
    const float* W0  = (const float*)d_in[1];
    const float* W1  = (const float*)d_in[2];
    const float* W2  = (const float*)d_in[3];
    const float* M0w = (const float*)d_in[4];
    const float* M0b = (const float*)d_in[5];
    const float* M1w = (const float*)d_in[6];
    const float* M1b = (const float*)d_in[7];
    const void*  ei  = d_in[8];
    const void*  bat = d_in[9];
    float* out = (float*)d_out;

    __half* hA = nullptr;
    __half* hB = nullptr;
    __half* w16 = nullptr;
    cudaGetSymbolAddress((void**)&hA, g_h16a);
    cudaGetSymbolAddress((void**)&hB, g_h16b);
    cudaGetSymbolAddress((void**)&w16, g_w16);

    static int attr_done = 0;
    if (!attr_done) {
        cudaFuncSetAttribute(k_gemm, cudaFuncAttributeMaxDynamicSharedMemorySize, SMEM_GEMM);
        cudaFuncSetAttribute(k_gemm_f32in, cudaFuncAttributeMaxDynamicSharedMemorySize, SMEM_GEMM);
        attr_done = 1;
    }

    const int T = 256;
    int gZ = (PADDEG + T - 1) / T;          // 208
    int gN = (NN + T - 1) / T;              // 196
    int gE = (EE + T - 1) / T;              // 3125
    int gGemm   = (NN + 127) / 128;         // 391
    int gGather = (NN * 16 + T - 1) / T;    // 3125
    int gW      = (3 * HH * HH / 4 + T - 1) / T;   // 48

    // profiled launch is index 3 -> k_scan this round
    k_zero<<<gZ, T>>>();                                        // 0
    k_detect<<<1, 256>>>((const int*)ei);                       // 1
    k_hist<<<gE, T>>>(ei);                                      // 2
    k_scan<<<1, 1024>>>();                                      // 3  <- profiled
    k_fill<<<gE, T>>>(ei);                                      // 4
    k_cvtw<<<gW, T>>>(W0, W1, W2);                              // 5
    k_gemm_f32in<<<gGemm, T, SMEM_GEMM>>>(x, w16, hB, NN);      // 6
    k_cvt_batch<<<gN, T>>>(bat);                                // 7

    k_gather<<<gGather, T>>>(hB, hA, 1);                        // layer 1 agg
    k_gemm<<<gGemm, T, SMEM_GEMM>>>(hA, w16 + HH * HH, hB, NN);
    k_gather<<<gGather, T>>>(hB, hA, 1);                        // layer 2
    k_gemm<<<gGemm, T, SMEM_GEMM>>>(hA, w16 + 2 * HH * HH, hB, NN);
    k_gather<<<gGather, T>>>(hB, hA, 0);                        // layer 3

    k_pool<<<(NN + 255) / 256, 128>>>(hA);
    k_mlp<<<GG, 128>>>(M0w, M0b, M1w, M1b, out);
}

// round 9
// speedup vs baseline: 2.6619x; 1.5858x over previous
#include <cuda_runtime.h>
#include <cuda_fp16.h>
#include <mma.h>
#include <cstdint>

using namespace nvcuda;

#define NN   50000
#define PADN 50176
#define PADDEG 53248
#define NBLK 208                 // PADDEG / 256
#define EE   800000
#define HH   128
#define GG   64
#define OUTD 10

// ---------------- scratch (device globals; no dynamic allocation) ----------
__device__ __half g_h16a[(size_t)PADN * HH];  // gemm input / gather output
__device__ __half g_h16b[(size_t)PADN * HH];  // gemm output / gather input
__device__ __half g_w16[3 * HH * HH];         // fp16 weights
__device__ int    g_batch[NN];
__device__ int    g_deg[PADDEG];              // padded, zeroed
__device__ int    g_rowstart[NN + 1];
__device__ int    g_cursor[NN];
__device__ float  g_dinv[NN];
__device__ int    g_csri[EE];                 // src index only
__device__ int    g_bsum[NBLK];
__device__ int    g_boff[NBLK];
__device__ float  g_pooled[GG * HH];
__device__ float  g_cnts[GG];
__device__ int    g_is64;

// ---------------- edge decode helper ----------------------------------------
__device__ __forceinline__ void decode_edge(const void* p, int e, int& s, int& d) {
    if (g_is64) {
        const long long* q = (const long long*)p;
        s = (int)q[e];
        d = (int)q[EE + e];
    } else {
        const int* q = (const int*)p;
        s = q[e];
        d = q[EE + e];
    }
    s = min(max(s, 0), NN - 1);
    d = min(max(d, 0), NN - 1);
}

// ---------------- setup -----------------------------------------------------
__global__ void k_zero() {
    int i = blockIdx.x * blockDim.x + threadIdx.x;
    if (i < PADDEG) g_deg[i] = 0;
    if (i < GG * HH) g_pooled[i] = 0.0f;
    if (i < GG) g_cnts[i] = 0.0f;
}

__global__ void k_cvtw(const float* __restrict__ W0,
                       const float* __restrict__ W1,
                       const float* __restrict__ W2) {
    const int WQ = HH * HH / 4;          // 4096
    int i = blockIdx.x * blockDim.x + threadIdx.x;
    if (i >= 3 * WQ) return;
    const float4* src;
    int off;
    if (i < WQ)          { src = (const float4*)W0; off = i; }
    else if (i < 2 * WQ) { src = (const float4*)W1; off = i - WQ; }
    else                 { src = (const float4*)W2; off = i - 2 * WQ; }
    float4 v = src[off];
    __half2 a = __floats2half2_rn(v.x, v.y);
    __half2 b = __floats2half2_rn(v.z, v.w);
    uint2 o;
    o.x = *(unsigned int*)&a;
    o.y = *(unsigned int*)&b;
    ((uint2*)g_w16)[i] = o;
}

__global__ void k_detect(const int* __restrict__ p) {
    __shared__ int any;
    if (threadIdx.x == 0) any = 0;
    __syncthreads();
    int v = 0;
    for (int i = threadIdx.x; i < 4096; i += blockDim.x) v |= p[2 * i + 1];
    if (v) atomicOr(&any, 1);
    __syncthreads();
    if (threadIdx.x == 0) g_is64 = any ? 0 : 1;
}

__global__ void k_hist(const void* __restrict__ p) {
    int e = blockIdx.x * blockDim.x + threadIdx.x;
    if (e >= EE) return;
    int s, d;
    decode_edge(p, e, s, d);
    atomicAdd(&g_deg[d], 1);
}

// convert batch AND count nodes-per-graph, warp-aggregated
__global__ void k_cvt_batch(const void* __restrict__ p) {
    int n = blockIdx.x * blockDim.x + threadIdx.x;
    if (n >= NN) return;
    int b;
    if (g_is64) b = (int)((const long long*)p)[n];
    else        b = ((const int*)p)[n];
    b = min(max(b, 0), GG - 1);
    g_batch[n] = b;
    unsigned am = __activemask();
    unsigned mask = __match_any_sync(am, b);
    int leader = __ffs(mask) - 1;
    if ((threadIdx.x & 31) == leader)
        atomicAdd(&g_cnts[b], (float)__popc(mask));
}

// ---------------- parallel 3-phase scan --------------------------------------
// phase 1: per-block (256-entry) sums
__global__ void __launch_bounds__(256) k_scan1() {
    __shared__ int sh[256];
    int t = threadIdx.x;
    int i = blockIdx.x * 256 + t;
    sh[t] = g_deg[i];
    __syncthreads();
#pragma unroll
    for (int off = 128; off > 0; off >>= 1) {
        if (t < off) sh[t] += sh[t + off];
        __syncthreads();
    }
    if (t == 0) g_bsum[blockIdx.x] = sh[0];
}

// phase 2: exclusive scan of the 208 block sums (single tiny block)
__global__ void __launch_bounds__(256) k_scan2() {
    __shared__ int sh[256];
    int t = threadIdx.x;
    int v = (t < NBLK) ? g_bsum[t] : 0;
    sh[t] = v;
    __syncthreads();
#pragma unroll
    for (int off = 1; off < 256; off <<= 1) {
        int u = (t >= off) ? sh[t - off] : 0;
        __syncthreads();
        sh[t] += u;
        __syncthreads();
    }
    if (t < NBLK) g_boff[t] = sh[t] - v;     // exclusive
}

// phase 3: intra-block exclusive scan + block offset; emit rowstart/cursor/dinv
__global__ void __launch_bounds__(256) k_scan3() {
    __shared__ int ws[8];
    int t = threadIdx.x;
    int i = blockIdx.x * 256 + t;
    int lane = t & 31, w = t >> 5;
    int v = g_deg[i];                        // padding zeros beyond NN
    int inc = v;
#pragma unroll
    for (int off = 1; off < 32; off <<= 1) {
        int u = __shfl_up_sync(0xffffffffu, inc, off);
        if (lane >= off) inc += u;
    }
    if (lane == 31) ws[w] = inc;
    __syncthreads();
    if (t == 0) {
        int run = 0;
#pragma unroll
        for (int k = 0; k < 8; k++) { int tmp = ws[k]; ws[k] = run; run += tmp; }
    }
    __syncthreads();
    int excl = inc - v + ws[w] + g_boff[blockIdx.x];
    if (i <= NN) g_rowstart[i] = excl;
    if (i < NN) {
        g_cursor[i] = excl;
        g_dinv[i] = rsqrtf((float)v + 1.0f);
    }
}

// re-reads edge_index, places src into CSR slots (4B per edge)
__global__ void k_fill(const void* __restrict__ p) {
    int e = blockIdx.x * blockDim.x + threadIdx.x;
    if (e >= EE) return;
    int s, d;
    decode_edge(p, e, s, d);
    int pos = atomicAdd(&g_cursor[d], 1);
    g_csri[pos] = s;
}

// ---------------- tensor-core GEMM -------------------------------------------
#define LDA 136
#define SMEM_GEMM (2 * 128 * LDA * (int)sizeof(__half))   // 69,632 B

template <typename LOADA>
__device__ __forceinline__ void gemm_body(LOADA loadA,
                                          const __half* __restrict__ W,
                                          __half* __restrict__ C,
                                          int nRows) {
    extern __shared__ __half sm[];
    __half* As = sm;                   // 128 x LDA
    __half* Ws = sm + 128 * LDA;       // 128 x LDA

    int tid  = threadIdx.x;
    int w    = tid >> 5;
    int row0 = blockIdx.x * 128;

    loadA(As, row0, tid, nRows);
#pragma unroll
    for (int i = 0; i < 8; i++) {
        int idx = tid + i * 256;
        int r  = idx >> 4;
        int c8 = idx & 15;
        uint4 v = *(const uint4*)(W + r * 128 + c8 * 8);
        *(uint4*)(Ws + r * LDA + c8 * 8) = v;
    }
    __syncthreads();

    int wr = w >> 1, wc = w & 1;
    int r0w = wr * 32, c0w = wc * 64;

    wmma::fragment<wmma::accumulator, 16, 16, 16, float> c[2][4];
#pragma unroll
    for (int i = 0; i < 2; i++)
#pragma unroll
        for (int j = 0; j < 4; j++) wmma::fill_fragment(c[i][j], 0.0f);

#pragma unroll
    for (int k0 = 0; k0 < 128; k0 += 16) {
        wmma::fragment<wmma::matrix_a, 16, 16, 16, __half, wmma::row_major> a[2];
        wmma::fragment<wmma::matrix_b, 16, 16, 16, __half, wmma::row_major> b[4];
#pragma unroll
        for (int i = 0; i < 2; i++)
            wmma::load_matrix_sync(a[i], As + (r0w + i * 16) * LDA + k0, LDA);
#pragma unroll
        for (int j = 0; j < 4; j++)
            wmma::load_matrix_sync(b[j], Ws + k0 * LDA + c0w + j * 16, LDA);
#pragma unroll
        for (int i = 0; i < 2; i++)
#pragma unroll
            for (int j = 0; j < 4; j++)
                wmma::mma_sync(c[i][j], a[i], b[j], c[i][j]);
    }

#pragma unroll
    for (int i = 0; i < 2; i++) {
#pragma unroll
        for (int j = 0; j < 4; j++) {
            wmma::fragment<wmma::accumulator, 16, 16, 16, __half> hc;
#pragma unroll
            for (int e = 0; e < hc.num_elements; e++)
                hc.x[e] = __float2half(c[i][j].x[e]);
            wmma::store_matrix_sync(C + (size_t)(row0 + r0w + i * 16) * 128 + c0w + j * 16,
                                    hc, 128, wmma::mem_row_major);
        }
    }
}

__global__ void __launch_bounds__(256) k_gemm(const __half* __restrict__ A,
                                              const __half* __restrict__ W,
                                              __half* __restrict__ C,
                                              int nRows) {
    gemm_body([A](__half* As, int row0, int tid, int nR) {
#pragma unroll
        for (int i = 0; i < 8; i++) {
            int idx = tid + i * 256;
            int r  = idx >> 4;
            int c8 = idx & 15;
            uint4 v = make_uint4(0u, 0u, 0u, 0u);
            if (row0 + r < nR)
                v = *(const uint4*)(A + (size_t)(row0 + r) * 128 + c8 * 8);
            *(uint4*)(As + r * LDA + c8 * 8) = v;
        }
    }, W, C, nRows);
}

__global__ void __launch_bounds__(256) k_gemm_f32in(const float* __restrict__ A,
                                                    const __half* __restrict__ W,
                                                    __half* __restrict__ C,
                                                    int nRows) {
    gemm_body([A](__half* As, int row0, int tid, int nR) {
#pragma unroll
        for (int i = 0; i < 16; i++) {
            int idx = tid + i * 256;
            int r  = idx >> 5;
            int c4 = idx & 31;
            float4 v = make_float4(0.f, 0.f, 0.f, 0.f);
            if (row0 + r < nR)
                v = *(const float4*)(A + (size_t)(row0 + r) * 128 + c4 * 4);
            __half2 a = __floats2half2_rn(v.x, v.y);
            __half2 b = __floats2half2_rn(v.z, v.w);
            uint2 o;
            o.x = *(unsigned int*)&a;
            o.y = *(unsigned int*)&b;
            *(uint2*)(As + r * LDA + c4 * 4) = o;
        }
    }, W, C, nRows);
}

// ---------------- CSR gather: half-warp per node, src-only CSR --------------
// out[n] = dinv[n] * ( sum_s dinv[s]*h[s] + dinv[n]*h[n] )
__device__ __forceinline__ void unp8(uint4 v, float* f) {
    float2 a = __half22float2(*(__half2*)&v.x);
    float2 b = __half22float2(*(__half2*)&v.y);
    float2 c = __half22float2(*(__half2*)&v.z);
    float2 d = __half22float2(*(__half2*)&v.w);
    f[0] = a.x; f[1] = a.y; f[2] = b.x; f[3] = b.y;
    f[4] = c.x; f[5] = c.y; f[6] = d.x; f[7] = d.y;
}

__global__ void __launch_bounds__(256) k_gather(const __half* __restrict__ h,
                                                __half* __restrict__ out,
                                                int doRelu) {
    int hw   = (blockIdx.x * blockDim.x + threadIdx.x) >> 4;
    int lane = threadIdx.x & 15;
    if (hw >= NN) return;
    int n = hw;

    const uint4* h4 = (const uint4*)h;
    float di = g_dinv[n];
    float acc[8], f0[8], f1[8], f2[8], f3[8];
    unp8(h4[(size_t)n * 16 + lane], acc);
#pragma unroll
    for (int k = 0; k < 8; k++) acc[k] *= di;   // self term: di*h[n]

    int i   = g_rowstart[n];
    int end = g_rowstart[n + 1];
    for (; i + 3 < end; i += 4) {
        int s0 = g_csri[i],     s1 = g_csri[i + 1];
        int s2 = g_csri[i + 2], s3 = g_csri[i + 3];
        float w0 = __ldg(&g_dinv[s0]), w1 = __ldg(&g_dinv[s1]);
        float w2 = __ldg(&g_dinv[s2]), w3 = __ldg(&g_dinv[s3]);
        uint4 v0 = h4[(size_t)s0 * 16 + lane];
        uint4 v1 = h4[(size_t)s1 * 16 + lane];
        uint4 v2 = h4[(size_t)s2 * 16 + lane];
        uint4 v3 = h4[(size_t)s3 * 16 + lane];
        unp8(v0, f0); unp8(v1, f1); unp8(v2, f2); unp8(v3, f3);
#pragma unroll
        for (int k = 0; k < 8; k++)
            acc[k] += w0 * f0[k] + w1 * f1[k] + w2 * f2[k] + w3 * f3[k];
    }
    for (; i < end; i++) {
        int s0 = g_csri[i];
        float w0 = __ldg(&g_dinv[s0]);
        uint4 v0 = h4[(size_t)s0 * 16 + lane];
        unp8(v0, f0);
#pragma unroll
        for (int k = 0; k < 8; k++) acc[k] += w0 * f0[k];
    }
#pragma unroll
    for (int k = 0; k < 8; k++) acc[k] *= di;
    if (doRelu) {
#pragma unroll
        for (int k = 0; k < 8; k++) acc[k] = fmaxf(acc[k], 0.0f);
    }
    __half2 p0 = __floats2half2_rn(acc[0], acc[1]);
    __half2 p1 = __floats2half2_rn(acc[2], acc[3]);
    __half2 p2 = __floats2half2_rn(acc[4], acc[5]);
    __half2 p3 = __floats2half2_rn(acc[6], acc[7]);
    uint4 o;
    o.x = *(unsigned int*)&p0;
    o.y = *(unsigned int*)&p1;
    o.z = *(unsigned int*)&p2;
    o.w = *(unsigned int*)&p3;
    ((uint4*)out)[(size_t)n * 16 + lane] = o;
}

// ---------------- pooling: warp per 64-node chunk, uint2 loads ---------------
__global__ void __launch_bounds__(128) k_pool(const __half* __restrict__ h) {
    int warp = threadIdx.x >> 5;
    int lane = threadIdx.x & 31;
    int n0 = blockIdx.x * 256 + warp * 64;
    if (n0 >= NN) return;
    int n1 = n0 + 64; if (n1 > NN) n1 = NN;

    const uint2* h2 = (const uint2*)h;
    float a0 = 0.f, a1 = 0.f, a2 = 0.f, a3 = 0.f;
    int g = g_batch[n0];
    for (int n = n0; n < n1; n++) {
        int b = g_batch[n];
        if (b != g) {
            int base = g * HH + lane * 4;
            atomicAdd(&g_pooled[base + 0], a0);
            atomicAdd(&g_pooled[base + 1], a1);
            atomicAdd(&g_pooled[base + 2], a2);
            atomicAdd(&g_pooled[base + 3], a3);
            a0 = a1 = a2 = a3 = 0.f;
            g = b;
        }
        uint2 v = h2[(size_t)n * 32 + lane];
        float2 x = __half22float2(*(__half2*)&v.x);
        float2 y = __half22float2(*(__half2*)&v.y);
        a0 += x.x; a1 += x.y; a2 += y.x; a3 += y.y;
    }
    int base = g * HH + lane * 4;
    atomicAdd(&g_pooled[base + 0], a0);
    atomicAdd(&g_pooled[base + 1], a1);
    atomicAdd(&g_pooled[base + 2], a2);
    atomicAdd(&g_pooled[base + 3], a3);
}

// ---------------- final MLP: one block per graph -----------------------------
__global__ void __launch_bounds__(128) k_mlp(const float* __restrict__ M0w,
                                             const float* __restrict__ M0b,
                                             const float* __restrict__ M1w,
                                             const float* __restrict__ M1b,
                                             float* __restrict__ out) {
    __shared__ float pv[HH];
    __shared__ float hid[HH];
    int g = blockIdx.x;
    int t = threadIdx.x;
    pv[t] = g_pooled[g * HH + t] / fmaxf(g_cnts[g], 1.0f);
    __syncthreads();
    float s = M0b[t];
#pragma unroll 8
    for (int k = 0; k < HH; k++) s += pv[k] * M0w[k * HH + t];
    hid[t] = fmaxf(s, 0.0f);
    __syncthreads();
    if (t < OUTD) {
        float s2 = M1b[t];
#pragma unroll 8
        for (int j = 0; j < HH; j++) s2 += hid[j] * M1w[j * OUTD + t];
        out[g * OUTD + t] = s2;
    }
}

// ---------------- launch ----------------------------------------------------
extern "C" void kernel_launch(void* const* d_in, const int* in_sizes, int n_in,
                              void* d_out, int out_size) {
    const float* x   = (const float*)d_in[0];
    const float* W0  = (const float*)d_in[1];
    const float* W1  = (const float*)d_in[2];
    const float* W2  = (const float*)d_in[3];
    const float* M0w = (const float*)d_in[4];
    const float* M0b = (const float*)d_in[5];
    const float* M1w = (const float*)d_in[6];
    const float* M1b = (const float*)d_in[7];
    const void*  ei  = d_in[8];
    const void*  bat = d_in[9];
    float* out = (float*)d_out;

    __half* hA = nullptr;
    __half* hB = nullptr;
    __half* w16 = nullptr;
    cudaGetSymbolAddress((void**)&hA, g_h16a);
    cudaGetSymbolAddress((void**)&hB, g_h16b);
    cudaGetSymbolAddress((void**)&w16, g_w16);

    static int attr_done = 0;
    if (!attr_done) {
        cudaFuncSetAttribute(k_gemm, cudaFuncAttributeMaxDynamicSharedMemorySize, SMEM_GEMM);
        cudaFuncSetAttribute(k_gemm_f32in, cudaFuncAttributeMaxDynamicSharedMemorySize, SMEM_GEMM);
        attr_done = 1;
    }

    const int T = 256;
    int gZ = (PADDEG + T - 1) / T;          // 208
    int gN = (NN + T - 1) / T;              // 196
    int gE = (EE + T - 1) / T;              // 3125
    int gGemm   = (NN + 127) / 128;         // 391
    int gGather = (NN * 16 + T - 1) / T;    // 3125
    int gW      = (3 * HH * HH / 4 + T - 1) / T;   // 48

    // profiled launch is index 3 -> k_scan1 this round
    k_zero<<<gZ, T>>>();                                        // 0
    k_detect<<<1, 256>>>((const int*)ei);                       // 1
    k_hist<<<gE, T>>>(ei);                                      // 2
    k_scan1<<<NBLK, 256>>>();                                   // 3  <- profiled
    k_scan2<<<1, 256>>>();                                      // 4
    k_scan3<<<NBLK, 256>>>();                                   // 5
    k_fill<<<gE, T>>>(ei);                                      // 6
    k_cvtw<<<gW, T>>>(W0, W1, W2);                              // 7
    k_gemm_f32in<<<gGemm, T, SMEM_GEMM>>>(x, w16, hB, NN);      // 8
    k_cvt_batch<<<gN, T>>>(bat);                                // 9

    k_gather<<<gGather, T>>>(hB, hA, 1);                        // layer 1 agg
    k_gemm<<<gGemm, T, SMEM_GEMM>>>(hA, w16 + HH * HH, hB, NN);
    k_gather<<<gGather, T>>>(hB, hA, 1);                        // layer 2
    k_gemm<<<gGemm, T, SMEM_GEMM>>>(hA, w16 + 2 * HH * HH, hB, NN);
    k_gather<<<gGather, T>>>(hB, hA, 0);                        // layer 3

    k_pool<<<(NN + 255) / 256, 128>>>(hA);
    k_mlp<<<GG, 128>>>(M0w, M0b, M1w, M1b, out);
}